// round 2
// baseline (speedup 1.0000x reference)
#include <cuda_runtime.h>
#include <math.h>

#define N 768
#define NT 50
#define NN (N*N)
#define SIGMA 0.1f
#define RES 100
#define NL 5
#define S_ITERS 13   // max squaring iterations: s <= 13 -> q = s-1 <= 12

// Taylor coefficients 1/k!
#define C0  1.0f
#define C1  1.0f
#define C2  0.5f
#define C3  (1.0f/6.0f)
#define C4  (1.0f/24.0f)
#define C5  (1.0f/120.0f)
#define C6  (1.0f/720.0f)
#define C7  (1.0f/5040.0f)
#define C8  (1.0f/40320.0f)
#define C9  (1.0f/362880.0f)
#define C10 (1.0f/3628800.0f)
#define C11 (1.0f/39916800.0f)
#define C12 (2.0876757e-9f)
#define C13 (1.6059044e-10f)
#define C14 (1.1470746e-11f)
#define C15 (7.6471637e-13f)

typedef unsigned long long ull;

// Scratch (static device arrays; ~710 MB total)
__device__ float g_dist[NN];
__device__ float g_r[NT*N];
__device__ float g_rmax[NT];
__device__ int   g_s[NT];
__device__ int   g_q[NT];
__device__ float g_scale[NT];
__device__ float g_maxdist;
__device__ float g_betti[NT];
// buffers: 0=M 1=M2 2=M3 3=M4 4/5 = ping-pong (Taylor result lands in 5)
__device__ float g_buf[6][(size_t)NT*NN];

__device__ __forceinline__ void atomicMaxF(float* addr, float v) {
    atomicMax((int*)addr, __float_as_int(v));   // valid for non-negative floats
}

__device__ __forceinline__ void fma2(ull& d, ull a, ull b) {
    asm("fma.rn.f32x2 %0, %1, %2, %0;" : "+l"(d) : "l"(a), "l"(b));
}

union F4U2 { float4 f4; ull u2[2]; };
union U2F2 { ull u; float2 f2; };

__global__ void init_kernel() {
    int t = threadIdx.x;
    if (t < NT) g_rmax[t] = 0.0f;
    if (t == 0) g_maxdist = 0.0f;
}

__global__ void dist_kernel(const float* __restrict__ pts) {
    __shared__ float p[N*3];
    for (int i = threadIdx.x; i < N*3; i += blockDim.x) p[i] = pts[i];
    __syncthreads();
    int idx = blockIdx.x * blockDim.x + threadIdx.x;
    float d = 0.0f;
    if (idx < NN) {
        int i = idx / N, j = idx - i*N;
        float dx = p[i*3+0] - p[j*3+0];
        float dy = p[i*3+1] - p[j*3+1];
        float dz = p[i*3+2] - p[j*3+2];
        d = sqrtf(dx*dx + dy*dy + dz*dz);
        g_dist[idx] = d;
    }
    __shared__ float red[256];
    red[threadIdx.x] = d;
    __syncthreads();
    for (int off = 128; off > 0; off >>= 1) {
        if (threadIdx.x < off) red[threadIdx.x] = fmaxf(red[threadIdx.x], red[threadIdx.x+off]);
        __syncthreads();
    }
    if (threadIdx.x == 0) atomicMaxF(&g_maxdist, red[0]);
}

// one block per (t, i): off-diagonal row sums of soft adjacency
__global__ void rowsum_kernel() {
    int bid = blockIdx.x;           // t*N + i
    int t = bid / N, i = bid - t*N;
    float th = ((float)t / (float)(NT-1)) * g_maxdist;
    const float* drow = g_dist + (size_t)i*N;
    float s = 0.0f;
    for (int j = threadIdx.x; j < N; j += blockDim.x) {
        if (j != i) {
            float e = expf((drow[j] - th) / SIGMA);
            s += 1.0f / (1.0f + e);
        }
    }
    __shared__ float red[128];
    red[threadIdx.x] = s;
    __syncthreads();
    for (int off = 64; off > 0; off >>= 1) {
        if (threadIdx.x < off) red[threadIdx.x] += red[threadIdx.x+off];
        __syncthreads();
    }
    if (threadIdx.x == 0) {
        g_r[bid] = red[0];
        atomicMaxF(&g_rmax[t], red[0]);
    }
}

__global__ void sq_kernel() {
    int t = threadIdx.x;
    if (t < NT) {
        float x = 2.0f * g_rmax[t] / SIGMA;   // ||L||_inf / sigma bound
        // scale to ||M|| <= 2 (degree-15 Taylor handles this fine)
        int s = 0;
        if (x > 2.0f) s = (int)ceilf(log2f(x * 0.5f));
        if (s < 0) s = 0;
        if (s > 14) s = 14;
        g_s[t] = s;
        g_q[t] = (s > 1) ? (s - 1) : 0;
        g_scale[t] = exp2f((float)(-s)) / SIGMA;
    }
}

// M = -L/(sigma*2^s): off-diag = +A_ij*scale, diag = -r_i*scale
__global__ void buildM_kernel() {
    int t = blockIdx.y;
    int idx = blockIdx.x * blockDim.x + threadIdx.x;
    if (idx >= NN) return;
    int i = idx / N, j = idx - i*N;
    float th = ((float)t / (float)(NT-1)) * g_maxdist;
    float sc = g_scale[t];
    float v;
    if (i == j) {
        v = -g_r[t*N + i] * sc;
    } else {
        float e = expf((g_dist[idx] - th) / SIGMA);
        v = sc / (1.0f + e);
    }
    g_buf[0][(size_t)t*NN + idx] = v;
}

// buf4 = C12*I + C13*M + C14*M2 + C15*M3
__global__ void elw_g3_kernel() {
    int t = blockIdx.y;
    int idx = blockIdx.x * blockDim.x + threadIdx.x;
    if (idx >= NN) return;
    int i = idx / N, j = idx - i*N;
    size_t o = (size_t)t*NN + idx;
    float v = C13*g_buf[0][o] + C14*g_buf[1][o] + C15*g_buf[2][o];
    if (i == j) v += C12;
    g_buf[4][o] = v;
}

#define ASTRIDE 260   // 256 + 4 pad; multiple of 4 (16B-aligned rows), odd mod 32 group

// Batched symmetric-output GEMM: C = A*B (+ optional gc0*I+gc1*M+gc2*M2+gc3*M3)
// Lower-triangle 128x128 tiles only, mirrored (all operands are polynomials in
// the same symmetric M). Inner loop uses packed fma.rn.f32x2 (FFMA2): the A
// operand is stored DUPLICATED in shared so each ld.shared.v4 yields two f32x2
// broadcast pairs with no register packing.
__global__ void __launch_bounds__(256) gemm_kernel(int ai, int bi, int ci, int addG,
                                                   float gc0, float gc1, float gc2, float gc3,
                                                   int iter)
{
    int t = blockIdx.z;
    if (iter >= 0 && iter >= g_q[t]) return;

    // decode lower-triangular tile index (21 tiles for 6x6)
    int r = 0, rem = blockIdx.x;
    while (rem > r) { rem -= (r + 1); r++; }
    int btr = r, btc = rem;            // tile row >= tile col

    const float* A = g_buf[ai] + (size_t)t*NN;
    const float* B = g_buf[bi] + (size_t)t*NN;
    float*       C = g_buf[ci] + (size_t)t*NN;

    __shared__ float As2[16][ASTRIDE];   // duplicated: As2[k][2m]=As2[k][2m+1]=A[m][k]
    __shared__ float Bs[16][128];

    int tid = threadIdx.x;
    int tx = tid & 15, ty = tid >> 4;
    int row0 = btr * 128, col0 = btc * 128;

    ull acc[8][4];
    #pragma unroll
    for (int i = 0; i < 8; i++)
        #pragma unroll
        for (int j = 0; j < 4; j++) acc[i][j] = 0ULL;

    for (int kk = 0; kk < N; kk += 16) {
        // A tile 128x16, transposed + duplicated into As2[k][2m(,+1)]
        #pragma unroll
        for (int l = 0; l < 2; l++) {
            int id = tid*2 + l;                 // 0..511
            int m = id >> 2, g4 = id & 3;
            float4 v = *(const float4*)&A[(size_t)(row0 + m)*N + kk + g4*4];
            *(float2*)&As2[g4*4+0][2*m] = make_float2(v.x, v.x);
            *(float2*)&As2[g4*4+1][2*m] = make_float2(v.y, v.y);
            *(float2*)&As2[g4*4+2][2*m] = make_float2(v.z, v.z);
            *(float2*)&As2[g4*4+3][2*m] = make_float2(v.w, v.w);
        }
        // B tile 16x128
        #pragma unroll
        for (int l = 0; l < 2; l++) {
            int id = tid*2 + l;
            int kb = id >> 5, f = id & 31;
            *(float4*)&Bs[kb][f*4] = *(const float4*)&B[(size_t)(kk + kb)*N + col0 + f*4];
        }
        __syncthreads();
        #pragma unroll
        for (int k = 0; k < 16; k++) {
            ull ad[8], bb[4];
            F4U2 t0, t1, t2, t3, u0, u1;
            t0.f4 = *(const float4*)&As2[k][ty*16];
            t1.f4 = *(const float4*)&As2[k][ty*16 + 4];
            t2.f4 = *(const float4*)&As2[k][ty*16 + 8];
            t3.f4 = *(const float4*)&As2[k][ty*16 + 12];
            ad[0]=t0.u2[0]; ad[1]=t0.u2[1]; ad[2]=t1.u2[0]; ad[3]=t1.u2[1];
            ad[4]=t2.u2[0]; ad[5]=t2.u2[1]; ad[6]=t3.u2[0]; ad[7]=t3.u2[1];
            u0.f4 = *(const float4*)&Bs[k][tx*8];
            u1.f4 = *(const float4*)&Bs[k][tx*8 + 4];
            bb[0]=u0.u2[0]; bb[1]=u0.u2[1]; bb[2]=u1.u2[0]; bb[3]=u1.u2[1];
            #pragma unroll
            for (int i = 0; i < 8; i++)
                #pragma unroll
                for (int j = 0; j < 4; j++)
                    fma2(acc[i][j], ad[i], bb[j]);
        }
        __syncthreads();
    }

    // unpack to scalar accf[8][8] (cols 2j, 2j+1 in each pair)
    float accf[8][8];
    #pragma unroll
    for (int i = 0; i < 8; i++)
        #pragma unroll
        for (int j = 0; j < 4; j++) {
            U2F2 w; w.u = acc[i][j];
            accf[i][2*j]   = w.f2.x;
            accf[i][2*j+1] = w.f2.y;
        }

    if (addG) {
        const float* M  = g_buf[0] + (size_t)t*NN;
        const float* M2 = g_buf[1] + (size_t)t*NN;
        const float* M3 = g_buf[2] + (size_t)t*NN;
        #pragma unroll
        for (int i = 0; i < 8; i++) {
            int rr = row0 + ty*8 + i;
            #pragma unroll
            for (int j = 0; j < 8; j++) {
                int cc = col0 + tx*8 + j;
                size_t o = (size_t)rr*N + cc;
                float g = gc1*M[o] + gc2*M2[o] + gc3*M3[o];
                if (rr == cc) g += gc0;
                accf[i][j] += g;
            }
        }
    }

    // store lower tile (coalesced)
    #pragma unroll
    for (int i = 0; i < 8; i++) {
        int rr = row0 + ty*8 + i;
        *(float4*)&C[(size_t)rr*N + col0 + tx*8]     = make_float4(accf[i][0], accf[i][1], accf[i][2], accf[i][3]);
        *(float4*)&C[(size_t)rr*N + col0 + tx*8 + 4] = make_float4(accf[i][4], accf[i][5], accf[i][6], accf[i][7]);
    }
    // mirror to upper tile
    if (btr != btc) {
        #pragma unroll
        for (int j = 0; j < 8; j++) {
            int cc = col0 + tx*8 + j;
            *(float4*)&C[(size_t)cc*N + row0 + ty*8]     = make_float4(accf[0][j], accf[1][j], accf[2][j], accf[3][j]);
            *(float4*)&C[(size_t)cc*N + row0 + ty*8 + 4] = make_float4(accf[4][j], accf[5][j], accf[6][j], accf[7][j]);
        }
    }
}

// betti[t] = s==0 ? tr(X) : ||X||_F^2   with X in buffer 5 (q even) or 4 (q odd)
__global__ void frob_kernel() {
    int t = blockIdx.x;
    int s = g_s[t], q = g_q[t];
    const float* X = g_buf[(q & 1) ? 4 : 5] + (size_t)t*NN;
    double acc = 0.0;
    if (s == 0) {
        for (int i = threadIdx.x; i < N; i += blockDim.x)
            acc += (double)X[(size_t)i*N + i];
    } else {
        for (int idx = threadIdx.x; idx < NN; idx += blockDim.x) {
            double v = X[idx];
            acc += v * v;
        }
    }
    __shared__ double red[256];
    red[threadIdx.x] = acc;
    __syncthreads();
    for (int off = 128; off > 0; off >>= 1) {
        if (threadIdx.x < off) red[threadIdx.x] += red[threadIdx.x+off];
        __syncthreads();
    }
    if (threadIdx.x == 0) g_betti[t] = (float)red[0];
}

__global__ void final_kernel(float* __restrict__ out) {
    __shared__ float b[NT];
    __shared__ float bi[RES], sm[RES], dv[RES];
    __shared__ float red;
    int tid = threadIdx.x;
    if (tid < NT) b[tid] = g_betti[tid];
    __syncthreads();
    if (tid < RES) {
        float pos = (float)(NT-1) * (float)tid / (float)(RES-1);
        int i0 = (int)floorf(pos);
        if (i0 > NT-2) i0 = NT-2;
        if (i0 < 0) i0 = 0;
        float fr = pos - (float)i0;
        bi[tid] = b[i0]*(1.0f - fr) + b[i0+1]*fr;
    }
    __syncthreads();
    if (tid == 0) {
        float m = bi[0];
        for (int i = 1; i < RES; i++) m = fmaxf(m, bi[i]);
        red = m;
    }
    __syncthreads();
    if (tid < RES) out[tid] = bi[tid] / (red + 1e-8f);

    for (int k = 1; k < NL; k++) {
        int ks = 2*k + 1;           // 3,5,7,9 (all < RES/4)
        int pad = ks / 2;
        __syncthreads();
        if (tid < RES) {
            float s = 0.0f;
            for (int u = -pad; u <= pad; u++) {
                int j = tid + u;
                j = max(0, min(RES-1, j));   // edge padding
                s += bi[j];
            }
            sm[tid] = s / (float)ks;
        }
        __syncthreads();
        if (tid < RES) {
            float d = (tid < RES-1) ? (sm[tid+1] - sm[tid]) : (sm[RES-1] - sm[RES-2]);
            dv[tid] = d;
        }
        __syncthreads();
        if (tid == 0) {
            float m = fabsf(dv[0]);
            for (int i = 1; i < RES; i++) m = fmaxf(m, fabsf(dv[i]));
            red = m;
        }
        __syncthreads();
        if (tid < RES) out[k*RES + tid] = dv[tid] / (red + 1e-8f);
    }
}

extern "C" void kernel_launch(void* const* d_in, const int* in_sizes, int n_in,
                              void* d_out, int out_size)
{
    const float* pts = (const float*)d_in[0];
    float* out = (float*)d_out;

    init_kernel<<<1, 64>>>();
    dist_kernel<<<NN/256, 256>>>(pts);
    rowsum_kernel<<<NT*N, 128>>>();
    sq_kernel<<<1, 64>>>();

    dim3 gE(NN/256, NT);
    buildM_kernel<<<gE, 256>>>();

    dim3 gG(21, 1, NT);
    // Taylor degree 15, Paterson-Stockmeyer q=4
    gemm_kernel<<<gG, 256>>>(0, 0, 1, 0, 0,0,0,0, -1);                 // M2 = M*M
    gemm_kernel<<<gG, 256>>>(1, 0, 2, 0, 0,0,0,0, -1);                 // M3 = M2*M
    gemm_kernel<<<gG, 256>>>(1, 1, 3, 0, 0,0,0,0, -1);                 // M4 = M2*M2
    elw_g3_kernel<<<gE, 256>>>();                                      // B4 = G3
    gemm_kernel<<<gG, 256>>>(3, 4, 5, 1, C8, C9, C10, C11, -1);        // B5 = M4*B4 + G2
    gemm_kernel<<<gG, 256>>>(3, 5, 4, 1, C4, C5, C6,  C7,  -1);        // B4 = M4*B5 + G1
    gemm_kernel<<<gG, 256>>>(3, 4, 5, 1, C0, C1, C2,  C3,  -1);        // B5 = M4*B4 + G0 = exp(M)

    // q = max(s-1,0) squarings; per-t gating inside kernel; ping-pong 5<->4
    for (int i = 0; i < S_ITERS; i++) {
        int src = (i & 1) ? 4 : 5;
        int dst = (i & 1) ? 5 : 4;
        gemm_kernel<<<gG, 256>>>(src, src, dst, 0, 0,0,0,0, i);
    }

    frob_kernel<<<NT, 256>>>();
    final_kernel<<<1, 128>>>(out);
}

// round 5
// speedup vs baseline: 1.3087x; 1.3087x over previous
#include <cuda_runtime.h>
#include <cuda_bf16.h>
#include <math.h>
#include <stdint.h>

#define N 768
#define NT 50
#define NN (N*N)
#define SIGMA 0.1f
#define RES 100
#define NL 5
#define S_ITERS 13      // s <= 14 -> q <= 13
#define KC 32
#define NCHUNK (N/KC)   // 24

// Taylor coefficients 1/k!
#define C0  1.0f
#define C1  1.0f
#define C2  0.5f
#define C3  (1.0f/6.0f)
#define C4  (1.0f/24.0f)
#define C5  (1.0f/120.0f)
#define C6  (1.0f/720.0f)
#define C7  (1.0f/5040.0f)
#define C8  (1.0f/40320.0f)
#define C9  (1.0f/362880.0f)
#define C10 (1.0f/3628800.0f)
#define C11 (1.0f/39916800.0f)
#define C12 (2.0876757e-9f)
#define C13 (1.6059044e-10f)
#define C14 (1.1470746e-11f)
#define C15 (7.6471637e-13f)

// ---------------- global scratch ----------------
__device__ float g_dist[NN];
__device__ float g_r[NT*N];
__device__ float g_rmax[NT];
__device__ int   g_s[NT];
__device__ int   g_q[NT];
__device__ float g_scale[NT];
__device__ float g_maxdist;
__device__ float g_betti[NT];
// fp32 buffers: 0=M 1=M2 2=M3 3=M4 4/5 = ping-pong
__device__ float g_buf[6][(size_t)NT*NN];
// bf16 limb planes (3 per buffer) for tensor-core operands.
// 16B-aligned: source of 16B cp.async + uint2 stores. Plane stride NT*NN*2 B
// is a multiple of 16, so every sub-plane base stays 16B-aligned.
__device__ __align__(16) __nv_bfloat16 g_limb[6][3][(size_t)NT*NN];

// ---------------- helpers ----------------
__device__ __forceinline__ void atomicMaxF(float* addr, float v) {
    atomicMax((int*)addr, __float_as_int(v));   // non-negative floats
}
__device__ __forceinline__ uint32_t smem_u32(const void* p) {
    uint32_t a;
    asm("{ .reg .u64 t; cvta.to.shared.u64 t, %1; cvt.u32.u64 %0, t; }" : "=r"(a) : "l"(p));
    return a;
}
__device__ __forceinline__ void cp16(uint32_t s, const void* g) {
    asm volatile("cp.async.cg.shared.global [%0], [%1], 16;" :: "r"(s), "l"(g));
}
#define CP_COMMIT() asm volatile("cp.async.commit_group;" ::: "memory")
#define CP_WAIT(n)  asm volatile("cp.async.wait_group %0;" :: "n"(n) : "memory")

__device__ __forceinline__ void ldm_x4(uint32_t* r, uint32_t addr) {
    asm volatile("ldmatrix.sync.aligned.m8n8.x4.shared.b16 {%0,%1,%2,%3}, [%4];"
                 : "=r"(r[0]), "=r"(r[1]), "=r"(r[2]), "=r"(r[3]) : "r"(addr));
}
__device__ __forceinline__ void mma16816(float* d, const uint32_t* a, const uint32_t* b) {
    asm volatile(
        "mma.sync.aligned.m16n8k16.row.col.f32.bf16.bf16.f32 "
        "{%0,%1,%2,%3}, {%4,%5,%6,%7}, {%8,%9}, {%0,%1,%2,%3};"
        : "+f"(d[0]), "+f"(d[1]), "+f"(d[2]), "+f"(d[3])
        : "r"(a[0]), "r"(a[1]), "r"(a[2]), "r"(a[3]), "r"(b[0]), "r"(b[1]));
}

__device__ __forceinline__ uint32_t pack2(__nv_bfloat16 lo, __nv_bfloat16 hi) {
    __nv_bfloat162 t = __halves2bfloat162(lo, hi);
    return *reinterpret_cast<uint32_t*>(&t);
}
__device__ __forceinline__ void split3(float x, __nv_bfloat16& a0, __nv_bfloat16& a1, __nv_bfloat16& a2) {
    a0 = __float2bfloat16_rn(x); float r = x - __bfloat162float(a0);
    a1 = __float2bfloat16_rn(r); r -= __bfloat162float(a1);
    a2 = __float2bfloat16_rn(r);
}
// pack 4 consecutive values of each limb into uint2 (4 x bf16)
__device__ __forceinline__ void split3x4(float4 v, uint2& L0, uint2& L1, uint2& L2) {
    __nv_bfloat16 a0,a1,a2,b0,b1,b2,c0,c1,c2,d0,d1,d2;
    split3(v.x, a0,a1,a2); split3(v.y, b0,b1,b2);
    split3(v.z, c0,c1,c2); split3(v.w, d0,d1,d2);
    L0 = make_uint2(pack2(a0,b0), pack2(c0,d0));
    L1 = make_uint2(pack2(a1,b1), pack2(c1,d1));
    L2 = make_uint2(pack2(a2,b2), pack2(c2,d2));
}

// ---------------- small kernels ----------------
__global__ void init_kernel() {
    int t = threadIdx.x;
    if (t < NT) g_rmax[t] = 0.0f;
    if (t == 0) g_maxdist = 0.0f;
}

__global__ void dist_kernel(const float* __restrict__ pts) {
    __shared__ float p[N*3];
    for (int i = threadIdx.x; i < N*3; i += blockDim.x) p[i] = pts[i];
    __syncthreads();
    int idx = blockIdx.x * blockDim.x + threadIdx.x;
    float d = 0.0f;
    if (idx < NN) {
        int i = idx / N, j = idx - i*N;
        float dx = p[i*3+0] - p[j*3+0];
        float dy = p[i*3+1] - p[j*3+1];
        float dz = p[i*3+2] - p[j*3+2];
        d = sqrtf(dx*dx + dy*dy + dz*dz);
        g_dist[idx] = d;
    }
    __shared__ float red[256];
    red[threadIdx.x] = d;
    __syncthreads();
    for (int off = 128; off > 0; off >>= 1) {
        if (threadIdx.x < off) red[threadIdx.x] = fmaxf(red[threadIdx.x], red[threadIdx.x+off]);
        __syncthreads();
    }
    if (threadIdx.x == 0) atomicMaxF(&g_maxdist, red[0]);
}

__global__ void rowsum_kernel() {
    int bid = blockIdx.x;           // t*N + i
    int t = bid / N, i = bid - t*N;
    float th = ((float)t / (float)(NT-1)) * g_maxdist;
    const float* drow = g_dist + (size_t)i*N;
    float s = 0.0f;
    for (int j = threadIdx.x; j < N; j += blockDim.x) {
        if (j != i) {
            float e = expf((drow[j] - th) / SIGMA);
            s += 1.0f / (1.0f + e);
        }
    }
    __shared__ float red[128];
    red[threadIdx.x] = s;
    __syncthreads();
    for (int off = 64; off > 0; off >>= 1) {
        if (threadIdx.x < off) red[threadIdx.x] += red[threadIdx.x+off];
        __syncthreads();
    }
    if (threadIdx.x == 0) {
        g_r[bid] = red[0];
        atomicMaxF(&g_rmax[t], red[0]);
    }
}

__global__ void sq_kernel() {
    int t = threadIdx.x;
    if (t < NT) {
        float x = 2.0f * g_rmax[t] / SIGMA;   // ||L||_inf / sigma bound
        int s = 0;
        if (x > 2.0f) s = (int)ceilf(log2f(x * 0.5f));   // scale to ||M|| <= 2
        if (s < 0) s = 0;
        if (s > 14) s = 14;
        g_s[t] = s;
        g_q[t] = (s > 1) ? (s - 1) : 0;
        g_scale[t] = exp2f((float)(-s)) / SIGMA;
    }
}

// M = -L/(sigma*2^s); also emit bf16 limbs of M
__global__ void buildM_kernel() {
    int t = blockIdx.y;
    int idx = blockIdx.x * blockDim.x + threadIdx.x;
    if (idx >= NN) return;
    int i = idx / N, j = idx - i*N;
    float th = ((float)t / (float)(NT-1)) * g_maxdist;
    float sc = g_scale[t];
    float v;
    if (i == j) {
        v = -g_r[t*N + i] * sc;
    } else {
        float e = expf((g_dist[idx] - th) / SIGMA);
        v = sc / (1.0f + e);
    }
    size_t o = (size_t)t*NN + idx;
    g_buf[0][o] = v;
    __nv_bfloat16 a0, a1, a2;
    split3(v, a0, a1, a2);
    g_limb[0][0][o] = a0; g_limb[0][1][o] = a1; g_limb[0][2][o] = a2;
}

// buf4 = C12*I + C13*M + C14*M2 + C15*M3 (+ limbs: buf4 is a GEMM operand)
__global__ void elw_g3_kernel() {
    int t = blockIdx.y;
    int idx = blockIdx.x * blockDim.x + threadIdx.x;
    if (idx >= NN) return;
    int i = idx / N, j = idx - i*N;
    size_t o = (size_t)t*NN + idx;
    float v = C13*g_buf[0][o] + C14*g_buf[1][o] + C15*g_buf[2][o];
    if (i == j) v += C12;
    g_buf[4][o] = v;
    __nv_bfloat16 a0, a1, a2;
    split3(v, a0, a1, a2);
    g_limb[4][0][o] = a0; g_limb[4][1][o] = a1; g_limb[4][2][o] = a2;
}

// ---------------- mma.sync batched GEMM ----------------
// smem: 2 buffers x 6 limb tiles; tile = 128 rows x 32 bf16, pitch 80B
#define TILEB 10240          // 128*80
#define BUFB  (6*TILEB)      // 61440
#define SMEMB (2*BUFB)       // 122880
#define CPIT  132            // C_sm pitch (floats); multiple of 4 -> 16B-aligned rows

__global__ void __launch_bounds__(256, 1) gemm_mma(int ai, int bi, int ci, int addG,
                                                   float gc0, float gc1, float gc2, float gc3,
                                                   int iter, int writeL)
{
    int t = blockIdx.z;
    if (iter >= 0 && iter >= g_q[t]) return;

    // lower-triangular tile decode (21 tiles of 6x6)
    int r = 0, rem = blockIdx.x;
    while (rem > r) { rem -= (r + 1); r++; }
    int btr = r, btc = rem;            // tile row >= tile col
    int row0 = btr * 128, col0 = btc * 128;

    extern __shared__ char smem[];
    uint32_t sb = smem_u32(smem);
    int tid = threadIdx.x;
    int wid = tid >> 5, lane = tid & 31;
    int wm = wid >> 2, wn = wid & 3;   // warp tile: rows wm*64, cols wn*32

    bool same = (ai == bi) && (btr == btc);
    const __nv_bfloat16* pA[3] = {
        g_limb[ai][0] + (size_t)t*NN, g_limb[ai][1] + (size_t)t*NN, g_limb[ai][2] + (size_t)t*NN };
    const __nv_bfloat16* pB[3] = {
        g_limb[bi][0] + (size_t)t*NN, g_limb[bi][1] + (size_t)t*NN, g_limb[bi][2] + (size_t)t*NN };
    float* C = g_buf[ci] + (size_t)t*NN;

    float acc[4][4][4];
    #pragma unroll
    for (int a = 0; a < 4; a++)
        #pragma unroll
        for (int b = 0; b < 4; b++)
            #pragma unroll
            for (int c = 0; c < 4; c++) acc[a][b][c] = 0.0f;

    // lane-invariant ldmatrix offsets
    uint32_t aLane = (uint32_t)((wm*64 + (lane & 15))*80 + ((lane >> 4)*16));
    uint32_t bLane = (uint32_t)((wn*32 + (lane & 7) + ((lane >> 4) << 3))*80 + (((lane >> 3) & 1)*16));
    const int nTiles = same ? 3 : 6;
    const int totCp = nTiles * 512;

    // ---- async-copy producer ----
    auto issue = [&](int c, int buf) {
        uint32_t bb = sb + buf*BUFB;
        int cK = c*KC;
        for (int idx = tid; idx < totCp; idx += 256) {
            int tile = idx >> 9;
            int rr2 = (idx & 511) >> 2, q = idx & 3;
            const __nv_bfloat16* src = (tile < 3)
                ? pA[tile] + (size_t)(row0 + rr2)*N + cK + q*8
                : pB[tile-3] + (size_t)(col0 + rr2)*N + cK + q*8;
            cp16(bb + tile*TILEB + rr2*80 + q*16, src);
        }
    };

    issue(0, 0); CP_COMMIT();

    const int PAo[6] = {0,0,0,1,1,2};
    const int PBo[6] = {0,1,2,0,1,0};

    for (int c = 0; c < NCHUNK; c++) {
        if (c + 1 < NCHUNK) { issue(c+1, (c+1)&1); CP_COMMIT(); CP_WAIT(1); }
        else CP_WAIT(0);
        __syncthreads();

        uint32_t bb  = sb + (c&1)*BUFB;
        uint32_t bbB = same ? bb : bb + 3*TILEB;
        #pragma unroll
        for (int ks = 0; ks < 2; ks++) {
            uint32_t af[4][4], bf[2][4];
            #pragma unroll
            for (int p = 0; p < 6; p++) {
                if (p == 0 || PAo[p] != PAo[p-1]) {
                    uint32_t base = bb + PAo[p]*TILEB + aLane + ks*32;
                    #pragma unroll
                    for (int mt = 0; mt < 4; mt++) ldm_x4(af[mt], base + mt*16*80);
                }
                {
                    uint32_t base = bbB + PBo[p]*TILEB + bLane + ks*32;
                    ldm_x4(bf[0], base);
                    ldm_x4(bf[1], base + 16*80);
                }
                #pragma unroll
                for (int mt = 0; mt < 4; mt++)
                    #pragma unroll
                    for (int nt = 0; nt < 4; nt++)
                        mma16816(acc[mt][nt], af[mt], &bf[nt>>1][(nt&1)*2]);
            }
        }
        __syncthreads();
    }

    // ---- epilogue via smem (coalesced stores + mirror + limb emission) ----
    float* C_sm = (float*)smem;
    {
        int g = lane >> 2, j2 = (lane & 3) * 2;
        #pragma unroll
        for (int mt = 0; mt < 4; mt++)
            #pragma unroll
            for (int nt = 0; nt < 4; nt++) {
                int rr = wm*64 + mt*16 + g;
                int cc = wn*32 + nt*8 + j2;
                C_sm[rr*CPIT + cc]       = acc[mt][nt][0];
                C_sm[rr*CPIT + cc + 1]   = acc[mt][nt][1];
                C_sm[(rr+8)*CPIT + cc]   = acc[mt][nt][2];
                C_sm[(rr+8)*CPIT + cc+1] = acc[mt][nt][3];
            }
    }
    __syncthreads();

    const float* Mp  = g_buf[0] + (size_t)t*NN;
    const float* M2p = g_buf[1] + (size_t)t*NN;
    const float* M3p = g_buf[2] + (size_t)t*NN;
    __nv_bfloat16* L0 = g_limb[ci][0] + (size_t)t*NN;
    __nv_bfloat16* L1 = g_limb[ci][1] + (size_t)t*NN;
    __nv_bfloat16* L2 = g_limb[ci][2] + (size_t)t*NN;

    {   // phase A: lower tile, row-coalesced
        int rr = tid & 127, h = tid >> 7;
        size_t rowOff = (size_t)(row0 + rr)*N + col0;
        #pragma unroll
        for (int i = 0; i < 16; i++) {
            int ce = h*64 + i*4;
            float4 v = *(float4*)&C_sm[rr*CPIT + ce];
            if (addG) {
                float4 m1 = *(const float4*)(Mp  + rowOff + ce);
                float4 m2 = *(const float4*)(M2p + rowOff + ce);
                float4 m3 = *(const float4*)(M3p + rowOff + ce);
                v.x += gc1*m1.x + gc2*m2.x + gc3*m3.x;
                v.y += gc1*m1.y + gc2*m2.y + gc3*m3.y;
                v.z += gc1*m1.z + gc2*m2.z + gc3*m3.z;
                v.w += gc1*m1.w + gc2*m2.w + gc3*m3.w;
                if (btr == btc) {
                    int k = rr - ce;
                    if (k >= 0 && k < 4) (&v.x)[k] += gc0;
                }
                if (btr != btc) *(float4*)&C_sm[rr*CPIT + ce] = v;  // mirror reads adjusted values
            }
            *(float4*)(C + rowOff + ce) = v;
            if (writeL) {
                uint2 l0, l1, l2;
                split3x4(v, l0, l1, l2);
                *(uint2*)(L0 + rowOff + ce) = l0;
                *(uint2*)(L1 + rowOff + ce) = l1;
                *(uint2*)(L2 + rowOff + ce) = l2;
            }
        }
    }
    if (btr != btc) {   // phase B: mirror (transpose out of smem)
        __syncthreads();
        int u = tid >> 1, hh = tid & 1;
        size_t rowOff = (size_t)(col0 + u)*N + row0;
        #pragma unroll
        for (int i = 0; i < 16; i++) {
            int x0 = hh*64 + i*4;
            float4 v = make_float4(C_sm[(x0  )*CPIT + u], C_sm[(x0+1)*CPIT + u],
                                   C_sm[(x0+2)*CPIT + u], C_sm[(x0+3)*CPIT + u]);
            *(float4*)(C + rowOff + x0) = v;
            if (writeL) {
                uint2 l0, l1, l2;
                split3x4(v, l0, l1, l2);
                *(uint2*)(L0 + rowOff + x0) = l0;
                *(uint2*)(L1 + rowOff + x0) = l1;
                *(uint2*)(L2 + rowOff + x0) = l2;
            }
        }
    }
}

// betti[t] = s==0 ? tr(X) : ||X||_F^2   with X in buffer 5 (q even) or 4 (q odd)
__global__ void frob_kernel() {
    int t = blockIdx.x;
    int s = g_s[t], q = g_q[t];
    const float* X = g_buf[(q & 1) ? 4 : 5] + (size_t)t*NN;
    double acc = 0.0;
    if (s == 0) {
        for (int i = threadIdx.x; i < N; i += blockDim.x)
            acc += (double)X[(size_t)i*N + i];
    } else {
        for (int idx = threadIdx.x; idx < NN; idx += blockDim.x) {
            double v = X[idx];
            acc += v * v;
        }
    }
    __shared__ double red[256];
    red[threadIdx.x] = acc;
    __syncthreads();
    for (int off = 128; off > 0; off >>= 1) {
        if (threadIdx.x < off) red[threadIdx.x] += red[threadIdx.x+off];
        __syncthreads();
    }
    if (threadIdx.x == 0) g_betti[t] = (float)red[0];
}

__global__ void final_kernel(float* __restrict__ out) {
    __shared__ float b[NT];
    __shared__ float bi[RES], sm[RES], dv[RES];
    __shared__ float red;
    int tid = threadIdx.x;
    if (tid < NT) b[tid] = g_betti[tid];
    __syncthreads();
    if (tid < RES) {
        float pos = (float)(NT-1) * (float)tid / (float)(RES-1);
        int i0 = (int)floorf(pos);
        if (i0 > NT-2) i0 = NT-2;
        if (i0 < 0) i0 = 0;
        float fr = pos - (float)i0;
        bi[tid] = b[i0]*(1.0f - fr) + b[i0+1]*fr;
    }
    __syncthreads();
    if (tid == 0) {
        float m = bi[0];
        for (int i = 1; i < RES; i++) m = fmaxf(m, bi[i]);
        red = m;
    }
    __syncthreads();
    if (tid < RES) out[tid] = bi[tid] / (red + 1e-8f);

    for (int k = 1; k < NL; k++) {
        int ks = 2*k + 1;
        int pad = ks / 2;
        __syncthreads();
        if (tid < RES) {
            float s = 0.0f;
            for (int u = -pad; u <= pad; u++) {
                int j = tid + u;
                j = max(0, min(RES-1, j));
                s += bi[j];
            }
            sm[tid] = s / (float)ks;
        }
        __syncthreads();
        if (tid < RES) {
            float d = (tid < RES-1) ? (sm[tid+1] - sm[tid]) : (sm[RES-1] - sm[RES-2]);
            dv[tid] = d;
        }
        __syncthreads();
        if (tid == 0) {
            float m = fabsf(dv[0]);
            for (int i = 1; i < RES; i++) m = fmaxf(m, fabsf(dv[i]));
            red = m;
        }
        __syncthreads();
        if (tid < RES) out[k*RES + tid] = dv[tid] / (red + 1e-8f);
    }
}

extern "C" void kernel_launch(void* const* d_in, const int* in_sizes, int n_in,
                              void* d_out, int out_size)
{
    const float* pts = (const float*)d_in[0];
    float* out = (float*)d_out;

    cudaFuncSetAttribute(gemm_mma, cudaFuncAttributeMaxDynamicSharedMemorySize, SMEMB);

    init_kernel<<<1, 64>>>();
    dist_kernel<<<NN/256, 256>>>(pts);
    rowsum_kernel<<<NT*N, 128>>>();
    sq_kernel<<<1, 64>>>();

    dim3 gE(NN/256, NT);
    buildM_kernel<<<gE, 256>>>();

    dim3 gG(21, 1, NT);
    // Taylor degree 15, Paterson-Stockmeyer q=4
    gemm_mma<<<gG, 256, SMEMB>>>(0, 0, 1, 0, 0,0,0,0, -1, 1);            // M2 = M*M      (limbs)
    gemm_mma<<<gG, 256, SMEMB>>>(1, 0, 2, 0, 0,0,0,0, -1, 0);            // M3 = M2*M     (fp32 only)
    gemm_mma<<<gG, 256, SMEMB>>>(1, 1, 3, 0, 0,0,0,0, -1, 1);            // M4 = M2*M2    (limbs)
    elw_g3_kernel<<<gE, 256>>>();                                        // B4 = G3       (limbs)
    gemm_mma<<<gG, 256, SMEMB>>>(3, 4, 5, 1, C8, C9, C10, C11, -1, 1);   // B5 = M4*B4 + G2
    gemm_mma<<<gG, 256, SMEMB>>>(3, 5, 4, 1, C4, C5, C6,  C7,  -1, 1);   // B4 = M4*B5 + G1
    gemm_mma<<<gG, 256, SMEMB>>>(3, 4, 5, 1, C0, C1, C2,  C3,  -1, 1);   // B5 = M4*B4 + G0 = exp(M)

    // q = max(s-1,0) squarings; per-t gating inside kernel; ping-pong 5<->4
    for (int i = 0; i < S_ITERS; i++) {
        int src = (i & 1) ? 4 : 5;
        int dst = (i & 1) ? 5 : 4;
        gemm_mma<<<gG, 256, SMEMB>>>(src, src, dst, 0, 0,0,0,0, i, 1);
    }

    frob_kernel<<<NT, 256>>>();
    final_kernel<<<1, 128>>>(out);
}

// round 6
// speedup vs baseline: 1.9090x; 1.4586x over previous
#include <cuda_runtime.h>
#include <cuda_bf16.h>
#include <cuda_fp16.h>
#include <math.h>
#include <stdint.h>

#define N 768
#define NT 50
#define NN (N*N)
#define SIGMA 0.1f
#define RES 100
#define NL 5
#define S_ITERS 12      // s <= 12 -> q <= 11 (theta = 4)
#define KC 32
#define NCHUNK (N/KC)   // 24

// Taylor coefficients 1/k!
#define C0  1.0f
#define C1  1.0f
#define C2  0.5f
#define C3  (1.0f/6.0f)
#define C4  (1.0f/24.0f)
#define C5  (1.0f/120.0f)
#define C6  (1.0f/720.0f)
#define C7  (1.0f/5040.0f)
#define C8  (1.0f/40320.0f)
#define C9  (1.0f/362880.0f)
#define C10 (1.0f/3628800.0f)
#define C11 (1.0f/39916800.0f)
#define C12 (2.0876757e-9f)
#define C13 (1.6059044e-10f)
#define C14 (1.1470746e-11f)
#define C15 (7.6471637e-13f)

// ---------------- global scratch ----------------
__device__ float g_dist[NN];
__device__ float g_r[NT*N];
__device__ float g_rmax[NT];
__device__ int   g_s[NT];
__device__ int   g_q[NT];
__device__ float g_scale[NT];
__device__ float g_maxdist;
__device__ float g_betti[NT];
// fp32 buffers: 0=M 1=M2 2=M3 3=M4 4/5 = ping-pong
__device__ float g_buf[6][(size_t)NT*NN];
// fp16 limb planes (2 per buffer) for tensor-core operands (16B-aligned:
// source of 16B cp.async + uint2 stores; plane stride NT*NN*2 B % 16 == 0)
__device__ __align__(16) __half g_limb[6][2][(size_t)NT*NN];

// ---------------- helpers ----------------
__device__ __forceinline__ void atomicMaxF(float* addr, float v) {
    atomicMax((int*)addr, __float_as_int(v));   // non-negative floats
}
__device__ __forceinline__ uint32_t smem_u32(const void* p) {
    uint32_t a;
    asm("{ .reg .u64 t; cvta.to.shared.u64 t, %1; cvt.u32.u64 %0, t; }" : "=r"(a) : "l"(p));
    return a;
}
__device__ __forceinline__ void cp16(uint32_t s, const void* g) {
    asm volatile("cp.async.cg.shared.global [%0], [%1], 16;" :: "r"(s), "l"(g));
}
#define CP_COMMIT() asm volatile("cp.async.commit_group;" ::: "memory")
#define CP_WAIT(n)  asm volatile("cp.async.wait_group %0;" :: "n"(n) : "memory")

__device__ __forceinline__ void ldm_x4(uint32_t* r, uint32_t addr) {
    asm volatile("ldmatrix.sync.aligned.m8n8.x4.shared.b16 {%0,%1,%2,%3}, [%4];"
                 : "=r"(r[0]), "=r"(r[1]), "=r"(r[2]), "=r"(r[3]) : "r"(addr));
}
__device__ __forceinline__ void mma16816(float* d, const uint32_t* a, const uint32_t* b) {
    asm volatile(
        "mma.sync.aligned.m16n8k16.row.col.f32.f16.f16.f32 "
        "{%0,%1,%2,%3}, {%4,%5,%6,%7}, {%8,%9}, {%0,%1,%2,%3};"
        : "+f"(d[0]), "+f"(d[1]), "+f"(d[2]), "+f"(d[3])
        : "r"(a[0]), "r"(a[1]), "r"(a[2]), "r"(a[3]), "r"(b[0]), "r"(b[1]));
}

__device__ __forceinline__ uint32_t packh(__half lo, __half hi) {
    __half2 t = __halves2half2(lo, hi);
    return *reinterpret_cast<uint32_t*>(&t);
}
__device__ __forceinline__ void split2(float x, __half& h0, __half& h1) {
    h0 = __float2half_rn(x);
    h1 = __float2half_rn(x - __half2float(h0));
}
// pack 4 consecutive values of each limb into uint2 (4 x fp16)
__device__ __forceinline__ void split2x4(float4 v, uint2& L0, uint2& L1) {
    __half a0,a1,b0,b1,c0,c1,d0,d1;
    split2(v.x, a0,a1); split2(v.y, b0,b1);
    split2(v.z, c0,c1); split2(v.w, d0,d1);
    L0 = make_uint2(packh(a0,b0), packh(c0,d0));
    L1 = make_uint2(packh(a1,b1), packh(c1,d1));
}

// ---------------- small kernels ----------------
__global__ void init_kernel() {
    int t = threadIdx.x;
    if (t < NT) g_rmax[t] = 0.0f;
    if (t == 0) g_maxdist = 0.0f;
}

__global__ void dist_kernel(const float* __restrict__ pts) {
    __shared__ float p[N*3];
    for (int i = threadIdx.x; i < N*3; i += blockDim.x) p[i] = pts[i];
    __syncthreads();
    int idx = blockIdx.x * blockDim.x + threadIdx.x;
    float d = 0.0f;
    if (idx < NN) {
        int i = idx / N, j = idx - i*N;
        float dx = p[i*3+0] - p[j*3+0];
        float dy = p[i*3+1] - p[j*3+1];
        float dz = p[i*3+2] - p[j*3+2];
        d = sqrtf(dx*dx + dy*dy + dz*dz);
        g_dist[idx] = d;
    }
    __shared__ float red[256];
    red[threadIdx.x] = d;
    __syncthreads();
    for (int off = 128; off > 0; off >>= 1) {
        if (threadIdx.x < off) red[threadIdx.x] = fmaxf(red[threadIdx.x], red[threadIdx.x+off]);
        __syncthreads();
    }
    if (threadIdx.x == 0) atomicMaxF(&g_maxdist, red[0]);
}

__global__ void rowsum_kernel() {
    int bid = blockIdx.x;           // t*N + i
    int t = bid / N, i = bid - t*N;
    float th = ((float)t / (float)(NT-1)) * g_maxdist;
    const float* drow = g_dist + (size_t)i*N;
    float s = 0.0f;
    for (int j = threadIdx.x; j < N; j += blockDim.x) {
        if (j != i) {
            float e = expf((drow[j] - th) / SIGMA);
            s += 1.0f / (1.0f + e);
        }
    }
    __shared__ float red[128];
    red[threadIdx.x] = s;
    __syncthreads();
    for (int off = 64; off > 0; off >>= 1) {
        if (threadIdx.x < off) red[threadIdx.x] += red[threadIdx.x+off];
        __syncthreads();
    }
    if (threadIdx.x == 0) {
        g_r[bid] = red[0];
        atomicMaxF(&g_rmax[t], red[0]);
    }
}

__global__ void sq_kernel() {
    int t = threadIdx.x;
    if (t < NT) {
        float x = 2.0f * g_rmax[t] / SIGMA;   // spectral bound ||L||/sigma
        int s = 0;
        if (x > 4.0f) s = (int)ceilf(log2f(x * 0.25f));   // scale to ||M|| <= 4
        if (s < 0) s = 0;
        if (s > 12) s = 12;
        g_s[t] = s;
        g_q[t] = (s > 1) ? (s - 1) : 0;
        g_scale[t] = exp2f((float)(-s)) / SIGMA;
    }
}

// M = -L/(sigma*2^s); also emit fp16 limbs of M
__global__ void buildM_kernel() {
    int t = blockIdx.y;
    int idx = blockIdx.x * blockDim.x + threadIdx.x;
    if (idx >= NN) return;
    int i = idx / N, j = idx - i*N;
    float th = ((float)t / (float)(NT-1)) * g_maxdist;
    float sc = g_scale[t];
    float v;
    if (i == j) {
        v = -g_r[t*N + i] * sc;
    } else {
        float e = expf((g_dist[idx] - th) / SIGMA);
        v = sc / (1.0f + e);
    }
    size_t o = (size_t)t*NN + idx;
    g_buf[0][o] = v;
    __half h0, h1;
    split2(v, h0, h1);
    g_limb[0][0][o] = h0; g_limb[0][1][o] = h1;
}

// buf4 = C12*I + C13*M + C14*M2 + C15*M3 (+ limbs: buf4 is a GEMM operand)
__global__ void elw_g3_kernel() {
    int t = blockIdx.y;
    int idx = blockIdx.x * blockDim.x + threadIdx.x;
    if (idx >= NN) return;
    int i = idx / N, j = idx - i*N;
    size_t o = (size_t)t*NN + idx;
    float v = C13*g_buf[0][o] + C14*g_buf[1][o] + C15*g_buf[2][o];
    if (i == j) v += C12;
    g_buf[4][o] = v;
    __half h0, h1;
    split2(v, h0, h1);
    g_limb[4][0][o] = h0; g_limb[4][1][o] = h1;
}

// ---------------- mma.sync batched GEMM (fp16 2-limb, 4 products) ----------------
// smem: 2 buffers x 4 limb tiles (A0 A1 B0 B1); tile = 128 rows x 32 fp16, pitch 80B
#define TILEB 10240          // 128*80
#define BUFB  (4*TILEB)      // 40960
#define SMEMB (2*BUFB)       // 81920
#define CPIT  132            // C_sm pitch (floats); multiple of 4 -> 16B rows

__global__ void __launch_bounds__(256, 1) gemm_mma(int ai, int bi, int ci, int addG,
                                                   float gc0, float gc1, float gc2, float gc3,
                                                   int iter, int writeL)
{
    int t = blockIdx.z;
    if (iter >= 0 && iter >= g_q[t]) return;

    // lower-triangular tile decode (21 tiles of 6x6)
    int r = 0, rem = blockIdx.x;
    while (rem > r) { rem -= (r + 1); r++; }
    int btr = r, btc = rem;            // tile row >= tile col
    int row0 = btr * 128, col0 = btc * 128;

    extern __shared__ char smem[];
    uint32_t sb = smem_u32(smem);
    int tid = threadIdx.x;
    int wid = tid >> 5, lane = tid & 31;
    int wm = wid >> 2, wn = wid & 3;   // warp tile: rows wm*64, cols wn*32

    bool same = (ai == bi) && (btr == btc);
    const __half* pA[2] = { g_limb[ai][0] + (size_t)t*NN, g_limb[ai][1] + (size_t)t*NN };
    const __half* pB[2] = { g_limb[bi][0] + (size_t)t*NN, g_limb[bi][1] + (size_t)t*NN };
    float* C = g_buf[ci] + (size_t)t*NN;

    float acc[4][4][4];
    #pragma unroll
    for (int a = 0; a < 4; a++)
        #pragma unroll
        for (int b = 0; b < 4; b++)
            #pragma unroll
            for (int c = 0; c < 4; c++) acc[a][b][c] = 0.0f;

    // lane-invariant ldmatrix offsets
    uint32_t aLane = (uint32_t)((wm*64 + (lane & 15))*80 + ((lane >> 4)*16));
    uint32_t bLane = (uint32_t)((wn*32 + (lane & 7) + ((lane >> 4) << 3))*80 + (((lane >> 3) & 1)*16));
    const int nTiles = same ? 2 : 4;
    const int totCp = nTiles * 512;

    // ---- async-copy producer ----
    auto issue = [&](int c, int buf) {
        uint32_t bb = sb + buf*BUFB;
        int cK = c*KC;
        for (int idx = tid; idx < totCp; idx += 256) {
            int tile = idx >> 9;
            int rr2 = (idx & 511) >> 2, q = idx & 3;
            const __half* src = (tile < 2)
                ? pA[tile] + (size_t)(row0 + rr2)*N + cK + q*8
                : pB[tile-2] + (size_t)(col0 + rr2)*N + cK + q*8;
            cp16(bb + tile*TILEB + rr2*80 + q*16, src);
        }
    };

    issue(0, 0); CP_COMMIT();

    for (int c = 0; c < NCHUNK; c++) {
        if (c + 1 < NCHUNK) { issue(c+1, (c+1)&1); CP_COMMIT(); CP_WAIT(1); }
        else CP_WAIT(0);
        __syncthreads();

        uint32_t bb  = sb + (c&1)*BUFB;
        uint32_t bbB = same ? bb : bb + 2*TILEB;
        #pragma unroll
        for (int ks = 0; ks < 2; ks++) {
            uint32_t af[4][4], bf0[2][4], bf1[2][4];
            {
                uint32_t base = bbB + bLane + ks*32;
                ldm_x4(bf0[0], base);            ldm_x4(bf0[1], base + 16*80);
                ldm_x4(bf1[0], base + TILEB);    ldm_x4(bf1[1], base + TILEB + 16*80);
            }
            #pragma unroll
            for (int ap = 0; ap < 2; ap++) {
                uint32_t base = bb + ap*TILEB + aLane + ks*32;
                #pragma unroll
                for (int mt = 0; mt < 4; mt++) ldm_x4(af[mt], base + mt*16*80);
                #pragma unroll
                for (int mt = 0; mt < 4; mt++)
                    #pragma unroll
                    for (int nt = 0; nt < 4; nt++) {
                        mma16816(acc[mt][nt], af[mt], &bf0[nt>>1][(nt&1)*2]);
                        mma16816(acc[mt][nt], af[mt], &bf1[nt>>1][(nt&1)*2]);
                    }
            }
        }
        __syncthreads();
    }

    // ---- epilogue via smem (coalesced stores + mirror + limb emission) ----
    float* C_sm = (float*)smem;
    {
        int g = lane >> 2, j2 = (lane & 3) * 2;
        #pragma unroll
        for (int mt = 0; mt < 4; mt++)
            #pragma unroll
            for (int nt = 0; nt < 4; nt++) {
                int rr = wm*64 + mt*16 + g;
                int cc = wn*32 + nt*8 + j2;
                C_sm[rr*CPIT + cc]       = acc[mt][nt][0];
                C_sm[rr*CPIT + cc + 1]   = acc[mt][nt][1];
                C_sm[(rr+8)*CPIT + cc]   = acc[mt][nt][2];
                C_sm[(rr+8)*CPIT + cc+1] = acc[mt][nt][3];
            }
    }
    __syncthreads();

    const float* Mp  = g_buf[0] + (size_t)t*NN;
    const float* M2p = g_buf[1] + (size_t)t*NN;
    const float* M3p = g_buf[2] + (size_t)t*NN;
    __half* L0 = g_limb[ci][0] + (size_t)t*NN;
    __half* L1 = g_limb[ci][1] + (size_t)t*NN;

    {   // phase A: lower tile, row-coalesced
        int rr = tid & 127, h = tid >> 7;
        size_t rowOff = (size_t)(row0 + rr)*N + col0;
        #pragma unroll
        for (int i = 0; i < 16; i++) {
            int ce = h*64 + i*4;
            float4 v = *(float4*)&C_sm[rr*CPIT + ce];
            if (addG) {
                float4 m1 = *(const float4*)(Mp  + rowOff + ce);
                float4 m2 = *(const float4*)(M2p + rowOff + ce);
                float4 m3 = *(const float4*)(M3p + rowOff + ce);
                v.x += gc1*m1.x + gc2*m2.x + gc3*m3.x;
                v.y += gc1*m1.y + gc2*m2.y + gc3*m3.y;
                v.z += gc1*m1.z + gc2*m2.z + gc3*m3.z;
                v.w += gc1*m1.w + gc2*m2.w + gc3*m3.w;
                if (btr == btc) {
                    int k = rr - ce;
                    if (k >= 0 && k < 4) (&v.x)[k] += gc0;
                }
                if (btr != btc) *(float4*)&C_sm[rr*CPIT + ce] = v;  // mirror reads adjusted
            }
            *(float4*)(C + rowOff + ce) = v;
            if (writeL) {
                uint2 l0, l1;
                split2x4(v, l0, l1);
                *(uint2*)(L0 + rowOff + ce) = l0;
                *(uint2*)(L1 + rowOff + ce) = l1;
            }
        }
    }
    if (btr != btc) {   // phase B: mirror (transpose out of smem)
        __syncthreads();
        int u = tid >> 1, hh = tid & 1;
        size_t rowOff = (size_t)(col0 + u)*N + row0;
        #pragma unroll
        for (int i = 0; i < 16; i++) {
            int x0 = hh*64 + i*4;
            float4 v = make_float4(C_sm[(x0  )*CPIT + u], C_sm[(x0+1)*CPIT + u],
                                   C_sm[(x0+2)*CPIT + u], C_sm[(x0+3)*CPIT + u]);
            *(float4*)(C + rowOff + x0) = v;
            if (writeL) {
                uint2 l0, l1;
                split2x4(v, l0, l1);
                *(uint2*)(L0 + rowOff + x0) = l0;
                *(uint2*)(L1 + rowOff + x0) = l1;
            }
        }
    }
}

// betti[t] = s==0 ? tr(X) : ||X||_F^2   with X in buffer 5 (q even) or 4 (q odd)
__global__ void frob_kernel() {
    int t = blockIdx.x;
    int s = g_s[t], q = g_q[t];
    const float* X = g_buf[(q & 1) ? 4 : 5] + (size_t)t*NN;
    double acc = 0.0;
    if (s == 0) {
        for (int i = threadIdx.x; i < N; i += blockDim.x)
            acc += (double)X[(size_t)i*N + i];
    } else {
        for (int idx = threadIdx.x; idx < NN; idx += blockDim.x) {
            double v = X[idx];
            acc += v * v;
        }
    }
    __shared__ double red[256];
    red[threadIdx.x] = acc;
    __syncthreads();
    for (int off = 128; off > 0; off >>= 1) {
        if (threadIdx.x < off) red[threadIdx.x] += red[threadIdx.x+off];
        __syncthreads();
    }
    if (threadIdx.x == 0) g_betti[t] = (float)red[0];
}

__global__ void final_kernel(float* __restrict__ out) {
    __shared__ float b[NT];
    __shared__ float bi[RES], sm[RES], dv[RES];
    __shared__ float red;
    int tid = threadIdx.x;
    if (tid < NT) b[tid] = g_betti[tid];
    __syncthreads();
    if (tid < RES) {
        float pos = (float)(NT-1) * (float)tid / (float)(RES-1);
        int i0 = (int)floorf(pos);
        if (i0 > NT-2) i0 = NT-2;
        if (i0 < 0) i0 = 0;
        float fr = pos - (float)i0;
        bi[tid] = b[i0]*(1.0f - fr) + b[i0+1]*fr;
    }
    __syncthreads();
    if (tid == 0) {
        float m = bi[0];
        for (int i = 1; i < RES; i++) m = fmaxf(m, bi[i]);
        red = m;
    }
    __syncthreads();
    if (tid < RES) out[tid] = bi[tid] / (red + 1e-8f);

    for (int k = 1; k < NL; k++) {
        int ks = 2*k + 1;
        int pad = ks / 2;
        __syncthreads();
        if (tid < RES) {
            float s = 0.0f;
            for (int u = -pad; u <= pad; u++) {
                int j = tid + u;
                j = max(0, min(RES-1, j));
                s += bi[j];
            }
            sm[tid] = s / (float)ks;
        }
        __syncthreads();
        if (tid < RES) {
            float d = (tid < RES-1) ? (sm[tid+1] - sm[tid]) : (sm[RES-1] - sm[RES-2]);
            dv[tid] = d;
        }
        __syncthreads();
        if (tid == 0) {
            float m = fabsf(dv[0]);
            for (int i = 1; i < RES; i++) m = fmaxf(m, fabsf(dv[i]));
            red = m;
        }
        __syncthreads();
        if (tid < RES) out[k*RES + tid] = dv[tid] / (red + 1e-8f);
    }
}

extern "C" void kernel_launch(void* const* d_in, const int* in_sizes, int n_in,
                              void* d_out, int out_size)
{
    const float* pts = (const float*)d_in[0];
    float* out = (float*)d_out;

    cudaFuncSetAttribute(gemm_mma, cudaFuncAttributeMaxDynamicSharedMemorySize, SMEMB);

    init_kernel<<<1, 64>>>();
    dist_kernel<<<NN/256, 256>>>(pts);
    rowsum_kernel<<<NT*N, 128>>>();
    sq_kernel<<<1, 64>>>();

    dim3 gE(NN/256, NT);
    buildM_kernel<<<gE, 256>>>();

    dim3 gG(21, 1, NT);
    // Taylor degree 15, Paterson-Stockmeyer q=4
    gemm_mma<<<gG, 256, SMEMB>>>(0, 0, 1, 0, 0,0,0,0, -1, 1);            // M2 = M*M      (limbs)
    gemm_mma<<<gG, 256, SMEMB>>>(1, 0, 2, 0, 0,0,0,0, -1, 0);            // M3 = M2*M     (fp32 only)
    gemm_mma<<<gG, 256, SMEMB>>>(1, 1, 3, 0, 0,0,0,0, -1, 1);            // M4 = M2*M2    (limbs)
    elw_g3_kernel<<<gE, 256>>>();                                        // B4 = G3       (limbs)
    gemm_mma<<<gG, 256, SMEMB>>>(3, 4, 5, 1, C8, C9, C10, C11, -1, 1);   // B5 = M4*B4 + G2
    gemm_mma<<<gG, 256, SMEMB>>>(3, 5, 4, 1, C4, C5, C6,  C7,  -1, 1);   // B4 = M4*B5 + G1
    gemm_mma<<<gG, 256, SMEMB>>>(3, 4, 5, 1, C0, C1, C2,  C3,  -1, 1);   // B5 = M4*B4 + G0 = exp(M)

    // q = max(s-1,0) squarings; per-t gating inside kernel; ping-pong 5<->4
    for (int i = 0; i < S_ITERS; i++) {
        int src = (i & 1) ? 4 : 5;
        int dst = (i & 1) ? 5 : 4;
        gemm_mma<<<gG, 256, SMEMB>>>(src, src, dst, 0, 0,0,0,0, i, 1);
    }

    frob_kernel<<<NT, 256>>>();
    final_kernel<<<1, 128>>>(out);
}

// round 7
// speedup vs baseline: 2.0958x; 1.0979x over previous
#include <cuda_runtime.h>
#include <cuda_fp16.h>
#include <math.h>
#include <stdint.h>

#define N 768
#define NT 50
#define NN (N*N)
#define SIGMA 0.1f
#define RES 100
#define NL 5
#define S_ITERS 12      // s <= 12 -> q <= 11 (theta = 4)
#define KC 32
#define NCHUNK (N/KC)   // 24

// Taylor coefficients 1/k!
#define C0  1.0f
#define C1  1.0f
#define C2  0.5f
#define C3  (1.0f/6.0f)
#define C4  (1.0f/24.0f)
#define C5  (1.0f/120.0f)
#define C6  (1.0f/720.0f)
#define C7  (1.0f/5040.0f)
#define C8  (1.0f/40320.0f)
#define C9  (1.0f/362880.0f)
#define C10 (1.0f/3628800.0f)
#define C11 (1.0f/39916800.0f)
#define C12 (2.0876757e-9f)
#define C13 (1.6059044e-10f)
#define C14 (1.1470746e-11f)
#define C15 (7.6471637e-13f)

// ---------------- global scratch ----------------
__device__ float g_dist[NN];
__device__ float g_r[NT*N];
__device__ float g_rmax[NT];
__device__ int   g_s[NT];
__device__ int   g_q[NT];
__device__ float g_scale[NT];
__device__ float g_maxdist;
__device__ float g_betti[NT];
// fp32 buffers: 0=M 1=M2 2=M3 3=M4 4/5 = ping-pong
__device__ float g_buf[6][(size_t)NT*NN];
// fp16 limb planes (2 per buffer); 16B-aligned for cp.async/uint2
__device__ __align__(16) __half g_limb[6][2][(size_t)NT*NN];

// ---------------- helpers ----------------
__device__ __forceinline__ void atomicMaxF(float* addr, float v) {
    atomicMax((int*)addr, __float_as_int(v));   // non-negative floats
}
__device__ __forceinline__ uint32_t smem_u32(const void* p) {
    uint32_t a;
    asm("{ .reg .u64 t; cvta.to.shared.u64 t, %1; cvt.u32.u64 %0, t; }" : "=r"(a) : "l"(p));
    return a;
}
__device__ __forceinline__ void cp16(uint32_t s, const void* g) {
    asm volatile("cp.async.cg.shared.global [%0], [%1], 16;" :: "r"(s), "l"(g));
}
#define CP_COMMIT() asm volatile("cp.async.commit_group;" ::: "memory")
#define CP_WAIT(n)  asm volatile("cp.async.wait_group %0;" :: "n"(n) : "memory")

__device__ __forceinline__ void ldm_x4(uint32_t* r, uint32_t addr) {
    asm volatile("ldmatrix.sync.aligned.m8n8.x4.shared.b16 {%0,%1,%2,%3}, [%4];"
                 : "=r"(r[0]), "=r"(r[1]), "=r"(r[2]), "=r"(r[3]) : "r"(addr));
}
__device__ __forceinline__ void mma16816(float* d, const uint32_t* a, const uint32_t* b) {
    asm volatile(
        "mma.sync.aligned.m16n8k16.row.col.f32.f16.f16.f32 "
        "{%0,%1,%2,%3}, {%4,%5,%6,%7}, {%8,%9}, {%0,%1,%2,%3};"
        : "+f"(d[0]), "+f"(d[1]), "+f"(d[2]), "+f"(d[3])
        : "r"(a[0]), "r"(a[1]), "r"(a[2]), "r"(a[3]), "r"(b[0]), "r"(b[1]));
}

__device__ __forceinline__ uint32_t packh(__half lo, __half hi) {
    __half2 t = __halves2half2(lo, hi);
    return *reinterpret_cast<uint32_t*>(&t);
}
__device__ __forceinline__ void split2(float x, __half& h0, __half& h1) {
    h0 = __float2half_rn(x);
    h1 = __float2half_rn(x - __half2float(h0));
}
__device__ __forceinline__ void split2x4(float4 v, uint2& L0, uint2& L1) {
    __half a0,a1,b0,b1,c0,c1,d0,d1;
    split2(v.x, a0,a1); split2(v.y, b0,b1);
    split2(v.z, c0,c1); split2(v.w, d0,d1);
    L0 = make_uint2(packh(a0,b0), packh(c0,d0));
    L1 = make_uint2(packh(a1,b1), packh(c1,d1));
}

// ---------------- small kernels ----------------
__global__ void init_kernel() {
    int t = threadIdx.x;
    if (t < NT) g_rmax[t] = 0.0f;
    if (t == 0) g_maxdist = 0.0f;
}

__global__ void dist_kernel(const float* __restrict__ pts) {
    __shared__ float p[N*3];
    for (int i = threadIdx.x; i < N*3; i += blockDim.x) p[i] = pts[i];
    __syncthreads();
    int idx = blockIdx.x * blockDim.x + threadIdx.x;
    float d = 0.0f;
    if (idx < NN) {
        int i = idx / N, j = idx - i*N;
        float dx = p[i*3+0] - p[j*3+0];
        float dy = p[i*3+1] - p[j*3+1];
        float dz = p[i*3+2] - p[j*3+2];
        d = sqrtf(dx*dx + dy*dy + dz*dz);
        g_dist[idx] = d;
    }
    __shared__ float red[256];
    red[threadIdx.x] = d;
    __syncthreads();
    for (int off = 128; off > 0; off >>= 1) {
        if (threadIdx.x < off) red[threadIdx.x] = fmaxf(red[threadIdx.x], red[threadIdx.x+off]);
        __syncthreads();
    }
    if (threadIdx.x == 0) atomicMaxF(&g_maxdist, red[0]);
}

__global__ void rowsum_kernel() {
    int bid = blockIdx.x;           // t*N + i
    int t = bid / N, i = bid - t*N;
    float th = ((float)t / (float)(NT-1)) * g_maxdist;
    const float* drow = g_dist + (size_t)i*N;
    float s = 0.0f;
    for (int j = threadIdx.x; j < N; j += blockDim.x) {
        if (j != i) {
            float e = expf((drow[j] - th) / SIGMA);
            s += 1.0f / (1.0f + e);
        }
    }
    __shared__ float red[128];
    red[threadIdx.x] = s;
    __syncthreads();
    for (int off = 64; off > 0; off >>= 1) {
        if (threadIdx.x < off) red[threadIdx.x] += red[threadIdx.x+off];
        __syncthreads();
    }
    if (threadIdx.x == 0) {
        g_r[bid] = red[0];
        atomicMaxF(&g_rmax[t], red[0]);
    }
}

__global__ void sq_kernel() {
    int t = threadIdx.x;
    if (t < NT) {
        float x = 2.0f * g_rmax[t] / SIGMA;   // spectral bound ||L||/sigma
        int s = 0;
        if (x > 4.0f) s = (int)ceilf(log2f(x * 0.25f));   // scale to ||M|| <= 4
        if (s < 0) s = 0;
        if (s > 12) s = 12;
        g_s[t] = s;
        g_q[t] = (s > 1) ? (s - 1) : 0;
        g_scale[t] = exp2f((float)(-s)) / SIGMA;
    }
}

// M = -L/(sigma*2^s); also emit fp16 limbs of M
__global__ void buildM_kernel() {
    int t = blockIdx.y;
    int idx = blockIdx.x * blockDim.x + threadIdx.x;
    if (idx >= NN) return;
    int i = idx / N, j = idx - i*N;
    float th = ((float)t / (float)(NT-1)) * g_maxdist;
    float sc = g_scale[t];
    float v;
    if (i == j) {
        v = -g_r[t*N + i] * sc;
    } else {
        float e = expf((g_dist[idx] - th) / SIGMA);
        v = sc / (1.0f + e);
    }
    size_t o = (size_t)t*NN + idx;
    g_buf[0][o] = v;
    __half h0, h1;
    split2(v, h0, h1);
    g_limb[0][0][o] = h0; g_limb[0][1][o] = h1;
}

// buf4 = C12*I + C13*M + C14*M2 + C15*M3 (+ limbs: buf4 is a GEMM operand)
__global__ void elw_g3_kernel() {
    int t = blockIdx.y;
    int idx = blockIdx.x * blockDim.x + threadIdx.x;
    if (idx >= NN) return;
    int i = idx / N, j = idx - i*N;
    size_t o = (size_t)t*NN + idx;
    float v = C13*g_buf[0][o] + C14*g_buf[1][o] + C15*g_buf[2][o];
    if (i == j) v += C12;
    g_buf[4][o] = v;
    __half h0, h1;
    split2(v, h0, h1);
    g_limb[4][0][o] = h0; g_limb[4][1][o] = h1;
}

// ---------------- mma.sync batched GEMM (fp16 2-limb, 3 products) ----------------
// smem: 2 buffers x 4 limb tiles (A0 A1 B0 B1); tile = 128 rows x 32 fp16, pitch 80B
#define TILEB 10240          // 128*80
#define BUFB  (4*TILEB)      // 40960
#define SMEMB (2*BUFB)       // 81920
#define CPIT  132            // C_sm pitch (floats); multiple of 4 -> 16B rows

__global__ void __launch_bounds__(256, 1) gemm_mma(int ai, int bi, int ci, int addG,
                                                   float gc0, float gc1, float gc2, float gc3,
                                                   int iter, int writeL)
{
    int t = blockIdx.z;
    if (iter >= 0 && iter >= g_q[t]) return;

    // lower-triangular tile decode (21 tiles of 6x6)
    int r = 0, rem = blockIdx.x;
    while (rem > r) { rem -= (r + 1); r++; }
    int btr = r, btc = rem;            // tile row >= tile col
    int row0 = btr * 128, col0 = btc * 128;

    extern __shared__ char smem[];
    uint32_t sb = smem_u32(smem);
    int tid = threadIdx.x;
    int wid = tid >> 5, lane = tid & 31;
    int wm = wid >> 2, wn = wid & 3;   // warp tile: rows wm*64, cols wn*32

    bool same = (ai == bi) && (btr == btc);
    const __half* pA[2] = { g_limb[ai][0] + (size_t)t*NN, g_limb[ai][1] + (size_t)t*NN };
    const __half* pB[2] = { g_limb[bi][0] + (size_t)t*NN, g_limb[bi][1] + (size_t)t*NN };
    float* C = g_buf[ci] + (size_t)t*NN;

    float acc[4][4][4];
    #pragma unroll
    for (int a = 0; a < 4; a++)
        #pragma unroll
        for (int b = 0; b < 4; b++)
            #pragma unroll
            for (int c = 0; c < 4; c++) acc[a][b][c] = 0.0f;

    // lane-invariant ldmatrix offsets
    uint32_t aLane = (uint32_t)((wm*64 + (lane & 15))*80 + ((lane >> 4)*16));
    uint32_t bLane = (uint32_t)((wn*32 + (lane & 7) + ((lane >> 4) << 3))*80 + (((lane >> 3) & 1)*16));
    const int nTiles = same ? 2 : 4;
    const int totCp = nTiles * 512;

    // ---- async-copy producer ----
    auto issue = [&](int c, int buf) {
        uint32_t bb = sb + buf*BUFB;
        int cK = c*KC;
        for (int idx = tid; idx < totCp; idx += 256) {
            int tile = idx >> 9;
            int rr2 = (idx & 511) >> 2, q = idx & 3;
            const __half* src = (tile < 2)
                ? pA[tile] + (size_t)(row0 + rr2)*N + cK + q*8
                : pB[tile-2] + (size_t)(col0 + rr2)*N + cK + q*8;
            cp16(bb + tile*TILEB + rr2*80 + q*16, src);
        }
    };

    issue(0, 0); CP_COMMIT();

    for (int c = 0; c < NCHUNK; c++) {
        if (c + 1 < NCHUNK) { issue(c+1, (c+1)&1); CP_COMMIT(); CP_WAIT(1); }
        else CP_WAIT(0);
        __syncthreads();

        uint32_t bb  = sb + (c&1)*BUFB;
        uint32_t bbB = same ? bb : bb + 2*TILEB;
        #pragma unroll
        for (int ks = 0; ks < 2; ks++) {
            uint32_t af0[4][4], af1[4][4], bf0[2][4], bf1[2][4];
            {
                uint32_t base = bbB + bLane + ks*32;
                ldm_x4(bf0[0], base);            ldm_x4(bf0[1], base + 16*80);
                ldm_x4(bf1[0], base + TILEB);    ldm_x4(bf1[1], base + TILEB + 16*80);
            }
            {
                uint32_t base = bb + aLane + ks*32;
                #pragma unroll
                for (int mt = 0; mt < 4; mt++) {
                    ldm_x4(af0[mt], base + mt*16*80);
                    ldm_x4(af1[mt], base + TILEB + mt*16*80);
                }
            }
            // 3 limb products: A0*B0, A0*B1, A1*B0  (A1*B1 ~ 2^-22, dropped)
            #pragma unroll
            for (int mt = 0; mt < 4; mt++)
                #pragma unroll
                for (int nt = 0; nt < 4; nt++) {
                    mma16816(acc[mt][nt], af0[mt], &bf0[nt>>1][(nt&1)*2]);
                    mma16816(acc[mt][nt], af0[mt], &bf1[nt>>1][(nt&1)*2]);
                    mma16816(acc[mt][nt], af1[mt], &bf0[nt>>1][(nt&1)*2]);
                }
        }
        __syncthreads();
    }

    // ---- epilogue via smem (coalesced stores + mirror + limb emission) ----
    float* C_sm = (float*)smem;
    {
        int g = lane >> 2, j2 = (lane & 3) * 2;
        #pragma unroll
        for (int mt = 0; mt < 4; mt++)
            #pragma unroll
            for (int nt = 0; nt < 4; nt++) {
                int rr = wm*64 + mt*16 + g;
                int cc = wn*32 + nt*8 + j2;
                C_sm[rr*CPIT + cc]       = acc[mt][nt][0];
                C_sm[rr*CPIT + cc + 1]   = acc[mt][nt][1];
                C_sm[(rr+8)*CPIT + cc]   = acc[mt][nt][2];
                C_sm[(rr+8)*CPIT + cc+1] = acc[mt][nt][3];
            }
    }
    __syncthreads();

    const float* Mp  = g_buf[0] + (size_t)t*NN;
    const float* M2p = g_buf[1] + (size_t)t*NN;
    const float* M3p = g_buf[2] + (size_t)t*NN;
    __half* L0 = g_limb[ci][0] + (size_t)t*NN;
    __half* L1 = g_limb[ci][1] + (size_t)t*NN;

    {   // phase A: lower tile, row-coalesced
        int rr = tid & 127, h = tid >> 7;
        size_t rowOff = (size_t)(row0 + rr)*N + col0;
        #pragma unroll
        for (int i = 0; i < 16; i++) {
            int ce = h*64 + i*4;
            float4 v = *(float4*)&C_sm[rr*CPIT + ce];
            if (addG) {
                float4 m1 = *(const float4*)(Mp  + rowOff + ce);
                float4 m2 = *(const float4*)(M2p + rowOff + ce);
                float4 m3 = *(const float4*)(M3p + rowOff + ce);
                v.x += gc1*m1.x + gc2*m2.x + gc3*m3.x;
                v.y += gc1*m1.y + gc2*m2.y + gc3*m3.y;
                v.z += gc1*m1.z + gc2*m2.z + gc3*m3.z;
                v.w += gc1*m1.w + gc2*m2.w + gc3*m3.w;
                if (btr == btc) {
                    int k = rr - ce;
                    if (k >= 0 && k < 4) (&v.x)[k] += gc0;
                }
                if (btr != btc) *(float4*)&C_sm[rr*CPIT + ce] = v;  // mirror reads adjusted
            }
            *(float4*)(C + rowOff + ce) = v;
            if (writeL) {
                uint2 l0, l1;
                split2x4(v, l0, l1);
                *(uint2*)(L0 + rowOff + ce) = l0;
                *(uint2*)(L1 + rowOff + ce) = l1;
            }
        }
    }
    if (btr != btc) {   // phase B: mirror (transpose out of smem)
        __syncthreads();
        int u = tid >> 1, hh = tid & 1;
        size_t rowOff = (size_t)(col0 + u)*N + row0;
        #pragma unroll
        for (int i = 0; i < 16; i++) {
            int x0 = hh*64 + i*4;
            float4 v = make_float4(C_sm[(x0  )*CPIT + u], C_sm[(x0+1)*CPIT + u],
                                   C_sm[(x0+2)*CPIT + u], C_sm[(x0+3)*CPIT + u]);
            *(float4*)(C + rowOff + x0) = v;
            if (writeL) {
                uint2 l0, l1;
                split2x4(v, l0, l1);
                *(uint2*)(L0 + rowOff + x0) = l0;
                *(uint2*)(L1 + rowOff + x0) = l1;
            }
        }
    }
}

// betti[t] = s==0 ? tr(X) : ||X||_F^2   with X in buffer 5 (q even) or 4 (q odd)
__global__ void frob_kernel() {
    int t = blockIdx.x;
    int s = g_s[t], q = g_q[t];
    const float* X = g_buf[(q & 1) ? 4 : 5] + (size_t)t*NN;
    double acc = 0.0;
    if (s == 0) {
        for (int i = threadIdx.x; i < N; i += blockDim.x)
            acc += (double)X[(size_t)i*N + i];
    } else {
        for (int idx = threadIdx.x; idx < NN; idx += blockDim.x) {
            double v = X[idx];
            acc += v * v;
        }
    }
    __shared__ double red[256];
    red[threadIdx.x] = acc;
    __syncthreads();
    for (int off = 128; off > 0; off >>= 1) {
        if (threadIdx.x < off) red[threadIdx.x] += red[threadIdx.x+off];
        __syncthreads();
    }
    if (threadIdx.x == 0) g_betti[t] = (float)red[0];
}

__global__ void final_kernel(float* __restrict__ out) {
    __shared__ float b[NT];
    __shared__ float bi[RES], sm[RES], dv[RES];
    __shared__ float red;
    int tid = threadIdx.x;
    if (tid < NT) b[tid] = g_betti[tid];
    __syncthreads();
    if (tid < RES) {
        float pos = (float)(NT-1) * (float)tid / (float)(RES-1);
        int i0 = (int)floorf(pos);
        if (i0 > NT-2) i0 = NT-2;
        if (i0 < 0) i0 = 0;
        float fr = pos - (float)i0;
        bi[tid] = b[i0]*(1.0f - fr) + b[i0+1]*fr;
    }
    __syncthreads();
    if (tid == 0) {
        float m = bi[0];
        for (int i = 1; i < RES; i++) m = fmaxf(m, bi[i]);
        red = m;
    }
    __syncthreads();
    if (tid < RES) out[tid] = bi[tid] / (red + 1e-8f);

    for (int k = 1; k < NL; k++) {
        int ks = 2*k + 1;
        int pad = ks / 2;
        __syncthreads();
        if (tid < RES) {
            float s = 0.0f;
            for (int u = -pad; u <= pad; u++) {
                int j = tid + u;
                j = max(0, min(RES-1, j));
                s += bi[j];
            }
            sm[tid] = s / (float)ks;
        }
        __syncthreads();
        if (tid < RES) {
            float d = (tid < RES-1) ? (sm[tid+1] - sm[tid]) : (sm[RES-1] - sm[RES-2]);
            dv[tid] = d;
        }
        __syncthreads();
        if (tid == 0) {
            float m = fabsf(dv[0]);
            for (int i = 1; i < RES; i++) m = fmaxf(m, fabsf(dv[i]));
            red = m;
        }
        __syncthreads();
        if (tid < RES) out[k*RES + tid] = dv[tid] / (red + 1e-8f);
    }
}

extern "C" void kernel_launch(void* const* d_in, const int* in_sizes, int n_in,
                              void* d_out, int out_size)
{
    const float* pts = (const float*)d_in[0];
    float* out = (float*)d_out;

    cudaFuncSetAttribute(gemm_mma, cudaFuncAttributeMaxDynamicSharedMemorySize, SMEMB);

    init_kernel<<<1, 64>>>();
    dist_kernel<<<NN/256, 256>>>(pts);
    rowsum_kernel<<<NT*N, 128>>>();
    sq_kernel<<<1, 64>>>();

    dim3 gE(NN/256, NT);
    buildM_kernel<<<gE, 256>>>();

    dim3 gG(21, 1, NT);
    // Taylor degree 15, Paterson-Stockmeyer q=4
    gemm_mma<<<gG, 256, SMEMB>>>(0, 0, 1, 0, 0,0,0,0, -1, 1);            // M2 = M*M      (limbs)
    gemm_mma<<<gG, 256, SMEMB>>>(1, 0, 2, 0, 0,0,0,0, -1, 0);            // M3 = M2*M     (fp32 only)
    gemm_mma<<<gG, 256, SMEMB>>>(1, 1, 3, 0, 0,0,0,0, -1, 1);            // M4 = M2*M2    (limbs)
    elw_g3_kernel<<<gE, 256>>>();                                        // B4 = G3       (limbs)
    gemm_mma<<<gG, 256, SMEMB>>>(3, 4, 5, 1, C8, C9, C10, C11, -1, 1);   // B5 = M4*B4 + G2
    gemm_mma<<<gG, 256, SMEMB>>>(3, 5, 4, 1, C4, C5, C6,  C7,  -1, 1);   // B4 = M4*B5 + G1
    gemm_mma<<<gG, 256, SMEMB>>>(3, 4, 5, 1, C0, C1, C2,  C3,  -1, 1);   // B5 = M4*B4 + G0 = exp(M)

    // q = max(s-1,0) squarings; per-t gating inside kernel; ping-pong 5<->4
    for (int i = 0; i < S_ITERS; i++) {
        int src = (i & 1) ? 4 : 5;
        int dst = (i & 1) ? 5 : 4;
        gemm_mma<<<gG, 256, SMEMB>>>(src, src, dst, 0, 0,0,0,0, i, 1);
    }

    frob_kernel<<<NT, 256>>>();
    final_kernel<<<1, 128>>>(out);
}

// round 10
// speedup vs baseline: 2.4974x; 1.1916x over previous
#include <cuda_runtime.h>
#include <cuda_fp16.h>
#include <math.h>
#include <stdint.h>

#define N 768
#define NT 50
#define NN (N*N)
#define SIGMA 0.1f
#define RES 100
#define NL 5
#define S_ITERS 12      // s <= 12 -> q <= 11 (theta = 4)
#define KC 32
#define NCHUNK (N/KC)   // 24

// Taylor coefficients 1/k!
#define C0  1.0f
#define C1  1.0f
#define C2  0.5f
#define C3  (1.0f/6.0f)
#define C4  (1.0f/24.0f)
#define C5  (1.0f/120.0f)
#define C6  (1.0f/720.0f)
#define C7  (1.0f/5040.0f)
#define C8  (1.0f/40320.0f)
#define C9  (1.0f/362880.0f)
#define C10 (1.0f/3628800.0f)
#define C11 (1.0f/39916800.0f)
#define C12 (2.0876757e-9f)
#define C13 (1.6059044e-10f)
#define C14 (1.1470746e-11f)
#define C15 (7.6471637e-13f)

// epilogue write modes
#define WM_NEVER  0
#define WM_ALWAYS 1
#define WM_LAST   2   // iff iter == q-1
#define WM_Q0     3   // iff q == 0
#define WM_NOTLAST 4  // iff iter < q-1

// ---------------- global scratch ----------------
__device__ float g_dist[NN];
__device__ float g_r[NT*N];
__device__ float g_rmax[NT];
__device__ int   g_s[NT];
__device__ int   g_q[NT];
__device__ float g_scale[NT];
__device__ float g_maxdist;
__device__ float g_betti[NT];
// fp32 buffers: 0=M 1=M2 2=M3 3=M4 4/5 = ping-pong
__device__ float g_buf[6][(size_t)NT*NN];
// fp16 limb planes (2 per buffer); 16B-aligned for cp.async/uint2
__device__ __align__(16) __half g_limb[6][2][(size_t)NT*NN];

// ---------------- helpers ----------------
__device__ __forceinline__ void atomicMaxF(float* addr, float v) {
    atomicMax((int*)addr, __float_as_int(v));   // non-negative floats
}
__device__ __forceinline__ uint32_t smem_u32(const void* p) {
    uint32_t a;
    asm("{ .reg .u64 t; cvta.to.shared.u64 t, %1; cvt.u32.u64 %0, t; }" : "=r"(a) : "l"(p));
    return a;
}
__device__ __forceinline__ void cp16(uint32_t s, const void* g) {
    asm volatile("cp.async.cg.shared.global [%0], [%1], 16;" :: "r"(s), "l"(g));
}
#define CP_COMMIT() asm volatile("cp.async.commit_group;" ::: "memory")
#define CP_WAIT(n)  asm volatile("cp.async.wait_group %0;" :: "n"(n) : "memory")

__device__ __forceinline__ void ldm_x4(uint32_t* r, uint32_t addr) {
    asm volatile("ldmatrix.sync.aligned.m8n8.x4.shared.b16 {%0,%1,%2,%3}, [%4];"
                 : "=r"(r[0]), "=r"(r[1]), "=r"(r[2]), "=r"(r[3]) : "r"(addr));
}
__device__ __forceinline__ void mma16816(float* d, const uint32_t* a, const uint32_t* b) {
    asm volatile(
        "mma.sync.aligned.m16n8k16.row.col.f32.f16.f16.f32 "
        "{%0,%1,%2,%3}, {%4,%5,%6,%7}, {%8,%9}, {%0,%1,%2,%3};"
        : "+f"(d[0]), "+f"(d[1]), "+f"(d[2]), "+f"(d[3])
        : "r"(a[0]), "r"(a[1]), "r"(a[2]), "r"(a[3]), "r"(b[0]), "r"(b[1]));
}

__device__ __forceinline__ uint32_t packh(__half lo, __half hi) {
    __half2 t = __halves2half2(lo, hi);
    return *reinterpret_cast<uint32_t*>(&t);
}
__device__ __forceinline__ void split2(float x, __half& h0, __half& h1) {
    h0 = __float2half_rn(x);
    h1 = __float2half_rn(x - __half2float(h0));
}
__device__ __forceinline__ void split2x4(float4 v, uint2& L0, uint2& L1) {
    __half a0,a1,b0,b1,c0,c1,d0,d1;
    split2(v.x, a0,a1); split2(v.y, b0,b1);
    split2(v.z, c0,c1); split2(v.w, d0,d1);
    L0 = make_uint2(packh(a0,b0), packh(c0,d0));
    L1 = make_uint2(packh(a1,b1), packh(c1,d1));
}

// ---------------- small kernels ----------------
__global__ void init_kernel() {
    int t = threadIdx.x;
    if (t < NT) g_rmax[t] = 0.0f;
    if (t == 0) g_maxdist = 0.0f;
}

__global__ void dist_kernel(const float* __restrict__ pts) {
    __shared__ float p[N*3];
    for (int i = threadIdx.x; i < N*3; i += blockDim.x) p[i] = pts[i];
    __syncthreads();
    int idx = blockIdx.x * blockDim.x + threadIdx.x;
    float d = 0.0f;
    if (idx < NN) {
        int i = idx / N, j = idx - i*N;
        float dx = p[i*3+0] - p[j*3+0];
        float dy = p[i*3+1] - p[j*3+1];
        float dz = p[i*3+2] - p[j*3+2];
        d = sqrtf(dx*dx + dy*dy + dz*dz);
        g_dist[idx] = d;
    }
    __shared__ float red[256];
    red[threadIdx.x] = d;
    __syncthreads();
    for (int off = 128; off > 0; off >>= 1) {
        if (threadIdx.x < off) red[threadIdx.x] = fmaxf(red[threadIdx.x], red[threadIdx.x+off]);
        __syncthreads();
    }
    if (threadIdx.x == 0) atomicMaxF(&g_maxdist, red[0]);
}

__global__ void rowsum_kernel() {
    int bid = blockIdx.x;           // t*N + i
    int t = bid / N, i = bid - t*N;
    float th = ((float)t / (float)(NT-1)) * g_maxdist;
    const float* drow = g_dist + (size_t)i*N;
    float s = 0.0f;
    for (int j = threadIdx.x; j < N; j += blockDim.x) {
        if (j != i) {
            float e = expf((drow[j] - th) / SIGMA);
            s += 1.0f / (1.0f + e);
        }
    }
    __shared__ float red[128];
    red[threadIdx.x] = s;
    __syncthreads();
    for (int off = 64; off > 0; off >>= 1) {
        if (threadIdx.x < off) red[threadIdx.x] += red[threadIdx.x+off];
        __syncthreads();
    }
    if (threadIdx.x == 0) {
        g_r[bid] = red[0];
        atomicMaxF(&g_rmax[t], red[0]);
    }
}

// Round-7 bound: lambda_max(L) <= 2*max_row_sum (Gershgorin).
// The slack in this bound is load-bearing: it keeps true ||M|| ~ theta/2,
// which the fp16-limb PS chain needs (round-8's tight bound pushed true
// ||M|| to ~4 and blew up high-order-term quantization error to 5e-3).
__global__ void sq_kernel() {
    int t = threadIdx.x;
    if (t < NT) {
        float x = 2.0f * g_rmax[t] / SIGMA;
        int s = 0;
        if (x > 4.0f) s = (int)ceilf(log2f(x * 0.25f));   // scale to ||M|| <= 4
        if (s < 0) s = 0;
        if (s > 12) s = 12;
        g_s[t] = s;
        g_q[t] = (s > 1) ? (s - 1) : 0;
        g_scale[t] = exp2f((float)(-s)) / SIGMA;
    }
}

// M = -L/(sigma*2^s); also emit fp16 limbs of M
__global__ void buildM_kernel() {
    int t = blockIdx.y;
    int idx = blockIdx.x * blockDim.x + threadIdx.x;
    if (idx >= NN) return;
    int i = idx / N, j = idx - i*N;
    float th = ((float)t / (float)(NT-1)) * g_maxdist;
    float sc = g_scale[t];
    float v;
    if (i == j) {
        v = -g_r[t*N + i] * sc;
    } else {
        float e = expf((g_dist[idx] - th) / SIGMA);
        v = sc / (1.0f + e);
    }
    size_t o = (size_t)t*NN + idx;
    g_buf[0][o] = v;
    __half h0, h1;
    split2(v, h0, h1);
    g_limb[0][0][o] = h0; g_limb[0][1][o] = h1;
}

// buf4 = C12*I + C13*M + C14*M2 + C15*M3 (limbs only; buf4 is a GEMM operand)
__global__ void elw_g3_kernel() {
    int t = blockIdx.y;
    int idx = blockIdx.x * blockDim.x + threadIdx.x;
    if (idx >= NN) return;
    int i = idx / N, j = idx - i*N;
    size_t o = (size_t)t*NN + idx;
    float v = C13*g_buf[0][o] + C14*g_buf[1][o] + C15*g_buf[2][o];
    if (i == j) v += C12;
    __half h0, h1;
    split2(v, h0, h1);
    g_limb[4][0][o] = h0; g_limb[4][1][o] = h1;
}

// ---------------- mma.sync batched GEMM (fp16 2-limb, 3 products) ----------------
// smem: 2 buffers x 4 limb tiles (A0 A1 B0 B1); tile = 128 rows x 32 fp16, pitch 80B
#define TILEB 10240          // 128*80
#define BUFB  (4*TILEB)      // 40960
#define SMEMB (2*BUFB)       // 81920
#define CPIT  132            // C_sm pitch (floats); multiple of 4 -> 16B rows

__global__ void __launch_bounds__(256, 2) gemm_mma(int ai, int bi, int ci, int addG,
                                                   float gc0, float gc1, float gc2, float gc3,
                                                   int iter, int fmode, int lmode)
{
    int t = blockIdx.z;
    int q = g_q[t];
    if (iter >= 0 && iter >= q) return;

    bool wF = (fmode == WM_ALWAYS) || (fmode == WM_LAST && iter == q-1) || (fmode == WM_Q0 && q == 0);
    bool wL = (lmode == WM_ALWAYS) || (lmode == WM_NOTLAST && iter < q-1);

    // lower-triangular tile decode (21 tiles of 6x6)
    int r = 0, rem = blockIdx.x;
    while (rem > r) { rem -= (r + 1); r++; }
    int btr = r, btc = rem;            // tile row >= tile col
    int row0 = btr * 128, col0 = btc * 128;

    extern __shared__ char smem[];
    uint32_t sb = smem_u32(smem);
    int tid = threadIdx.x;
    int wid = tid >> 5, lane = tid & 31;
    int wm = wid >> 2, wn = wid & 3;   // warp tile: rows wm*64, cols wn*32

    bool same = (ai == bi) && (btr == btc);
    const __half* pA[2] = { g_limb[ai][0] + (size_t)t*NN, g_limb[ai][1] + (size_t)t*NN };
    const __half* pB[2] = { g_limb[bi][0] + (size_t)t*NN, g_limb[bi][1] + (size_t)t*NN };
    float* C = g_buf[ci] + (size_t)t*NN;

    float acc[4][4][4];
    #pragma unroll
    for (int a = 0; a < 4; a++)
        #pragma unroll
        for (int b = 0; b < 4; b++)
            #pragma unroll
            for (int c = 0; c < 4; c++) acc[a][b][c] = 0.0f;

    // lane-invariant ldmatrix offsets
    uint32_t aLane = (uint32_t)((wm*64 + (lane & 15))*80 + ((lane >> 4)*16));
    uint32_t bLane = (uint32_t)((wn*32 + (lane & 7) + ((lane >> 4) << 3))*80 + (((lane >> 3) & 1)*16));
    const int nTiles = same ? 2 : 4;
    const int totCp = nTiles * 512;

    // ---- async-copy producer ----
    auto issue = [&](int c, int buf) {
        uint32_t bb = sb + buf*BUFB;
        int cK = c*KC;
        for (int idx = tid; idx < totCp; idx += 256) {
            int tile = idx >> 9;
            int rr2 = (idx & 511) >> 2, q2 = idx & 3;
            const __half* src = (tile < 2)
                ? pA[tile] + (size_t)(row0 + rr2)*N + cK + q2*8
                : pB[tile-2] + (size_t)(col0 + rr2)*N + cK + q2*8;
            cp16(bb + tile*TILEB + rr2*80 + q2*16, src);
        }
    };

    issue(0, 0); CP_COMMIT();

    for (int c = 0; c < NCHUNK; c++) {
        if (c + 1 < NCHUNK) { issue(c+1, (c+1)&1); CP_COMMIT(); CP_WAIT(1); }
        else CP_WAIT(0);
        __syncthreads();

        uint32_t bb  = sb + (c&1)*BUFB;
        uint32_t bbB = same ? bb : bb + 2*TILEB;
        #pragma unroll
        for (int ks = 0; ks < 2; ks++) {
            uint32_t af0[4][4], af1[4][4], bf0[2][4], bf1[2][4];
            {
                uint32_t base = bbB + bLane + ks*32;
                ldm_x4(bf0[0], base);            ldm_x4(bf0[1], base + 16*80);
                ldm_x4(bf1[0], base + TILEB);    ldm_x4(bf1[1], base + TILEB + 16*80);
            }
            {
                uint32_t base = bb + aLane + ks*32;
                #pragma unroll
                for (int mt = 0; mt < 4; mt++) {
                    ldm_x4(af0[mt], base + mt*16*80);
                    ldm_x4(af1[mt], base + TILEB + mt*16*80);
                }
            }
            // 3 limb products: A0*B0, A0*B1, A1*B0  (A1*B1 ~ 2^-22, dropped)
            #pragma unroll
            for (int mt = 0; mt < 4; mt++)
                #pragma unroll
                for (int nt = 0; nt < 4; nt++) {
                    mma16816(acc[mt][nt], af0[mt], &bf0[nt>>1][(nt&1)*2]);
                    mma16816(acc[mt][nt], af0[mt], &bf1[nt>>1][(nt&1)*2]);
                    mma16816(acc[mt][nt], af1[mt], &bf0[nt>>1][(nt&1)*2]);
                }
        }
        __syncthreads();
    }

    // ---- epilogue via smem (coalesced stores + mirror + limb emission) ----
    float* C_sm = (float*)smem;
    {
        int g = lane >> 2, j2 = (lane & 3) * 2;
        #pragma unroll
        for (int mt = 0; mt < 4; mt++)
            #pragma unroll
            for (int nt = 0; nt < 4; nt++) {
                int rr = wm*64 + mt*16 + g;
                int cc = wn*32 + nt*8 + j2;
                C_sm[rr*CPIT + cc]       = acc[mt][nt][0];
                C_sm[rr*CPIT + cc + 1]   = acc[mt][nt][1];
                C_sm[(rr+8)*CPIT + cc]   = acc[mt][nt][2];
                C_sm[(rr+8)*CPIT + cc+1] = acc[mt][nt][3];
            }
    }
    __syncthreads();

    const float* Mp  = g_buf[0] + (size_t)t*NN;
    const float* M2p = g_buf[1] + (size_t)t*NN;
    const float* M3p = g_buf[2] + (size_t)t*NN;
    __half* L0 = g_limb[ci][0] + (size_t)t*NN;
    __half* L1 = g_limb[ci][1] + (size_t)t*NN;

    {   // phase A: lower tile, row-coalesced
        int rr = tid & 127, h = tid >> 7;
        size_t rowOff = (size_t)(row0 + rr)*N + col0;
        #pragma unroll
        for (int i = 0; i < 16; i++) {
            int ce = h*64 + i*4;
            float4 v = *(float4*)&C_sm[rr*CPIT + ce];
            if (addG) {
                float4 m1 = *(const float4*)(Mp  + rowOff + ce);
                float4 m2 = *(const float4*)(M2p + rowOff + ce);
                float4 m3 = *(const float4*)(M3p + rowOff + ce);
                v.x += gc1*m1.x + gc2*m2.x + gc3*m3.x;
                v.y += gc1*m1.y + gc2*m2.y + gc3*m3.y;
                v.z += gc1*m1.z + gc2*m2.z + gc3*m3.z;
                v.w += gc1*m1.w + gc2*m2.w + gc3*m3.w;
                if (btr == btc) {
                    int k = rr - ce;
                    if (k >= 0 && k < 4) (&v.x)[k] += gc0;
                }
                if (btr != btc) *(float4*)&C_sm[rr*CPIT + ce] = v;  // mirror reads adjusted
            }
            if (wF) *(float4*)(C + rowOff + ce) = v;
            if (wL) {
                uint2 l0, l1;
                split2x4(v, l0, l1);
                *(uint2*)(L0 + rowOff + ce) = l0;
                *(uint2*)(L1 + rowOff + ce) = l1;
            }
        }
    }
    if (btr != btc) {   // phase B: mirror (transpose out of smem)
        __syncthreads();
        int u = tid >> 1, hh = tid & 1;
        size_t rowOff = (size_t)(col0 + u)*N + row0;
        #pragma unroll
        for (int i = 0; i < 16; i++) {
            int x0 = hh*64 + i*4;
            float4 v = make_float4(C_sm[(x0  )*CPIT + u], C_sm[(x0+1)*CPIT + u],
                                   C_sm[(x0+2)*CPIT + u], C_sm[(x0+3)*CPIT + u]);
            if (wF) *(float4*)(C + rowOff + x0) = v;
            if (wL) {
                uint2 l0, l1;
                split2x4(v, l0, l1);
                *(uint2*)(L0 + rowOff + x0) = l0;
                *(uint2*)(L1 + rowOff + x0) = l1;
            }
        }
    }
}

// betti[t] = s==0 ? tr(X) : ||X||_F^2   with X in buffer 5 (q even) or 4 (q odd)
__global__ void frob_kernel() {
    int t = blockIdx.x;
    int s = g_s[t], q = g_q[t];
    const float* X = g_buf[(q & 1) ? 4 : 5] + (size_t)t*NN;
    double acc = 0.0;
    if (s == 0) {
        for (int i = threadIdx.x; i < N; i += blockDim.x)
            acc += (double)X[(size_t)i*N + i];
    } else {
        for (int idx = threadIdx.x; idx < NN; idx += blockDim.x) {
            double v = X[idx];
            acc += v * v;
        }
    }
    __shared__ double red[256];
    red[threadIdx.x] = acc;
    __syncthreads();
    for (int off = 128; off > 0; off >>= 1) {
        if (threadIdx.x < off) red[threadIdx.x] += red[threadIdx.x+off];
        __syncthreads();
    }
    if (threadIdx.x == 0) g_betti[t] = (float)red[0];
}

__global__ void final_kernel(float* __restrict__ out) {
    __shared__ float b[NT];
    __shared__ float bi[RES], sm[RES], dv[RES];
    __shared__ float red;
    int tid = threadIdx.x;
    if (tid < NT) b[tid] = g_betti[tid];
    __syncthreads();
    if (tid < RES) {
        float pos = (float)(NT-1) * (float)tid / (float)(RES-1);
        int i0 = (int)floorf(pos);
        if (i0 > NT-2) i0 = NT-2;
        if (i0 < 0) i0 = 0;
        float fr = pos - (float)i0;
        bi[tid] = b[i0]*(1.0f - fr) + b[i0+1]*fr;
    }
    __syncthreads();
    if (tid == 0) {
        float m = bi[0];
        for (int i = 1; i < RES; i++) m = fmaxf(m, bi[i]);
        red = m;
    }
    __syncthreads();
    if (tid < RES) out[tid] = bi[tid] / (red + 1e-8f);

    for (int k = 1; k < NL; k++) {
        int ks = 2*k + 1;
        int pad = ks / 2;
        __syncthreads();
        if (tid < RES) {
            float s = 0.0f;
            for (int u = -pad; u <= pad; u++) {
                int j = tid + u;
                j = max(0, min(RES-1, j));
                s += bi[j];
            }
            sm[tid] = s / (float)ks;
        }
        __syncthreads();
        if (tid < RES) {
            float d = (tid < RES-1) ? (sm[tid+1] - sm[tid]) : (sm[RES-1] - sm[RES-2]);
            dv[tid] = d;
        }
        __syncthreads();
        if (tid == 0) {
            float m = fabsf(dv[0]);
            for (int i = 1; i < RES; i++) m = fmaxf(m, fabsf(dv[i]));
            red = m;
        }
        __syncthreads();
        if (tid < RES) out[k*RES + tid] = dv[tid] / (red + 1e-8f);
    }
}

extern "C" void kernel_launch(void* const* d_in, const int* in_sizes, int n_in,
                              void* d_out, int out_size)
{
    const float* pts = (const float*)d_in[0];
    float* out = (float*)d_out;

    cudaFuncSetAttribute(gemm_mma, cudaFuncAttributeMaxDynamicSharedMemorySize, SMEMB);

    init_kernel<<<1, 64>>>();
    dist_kernel<<<NN/256, 256>>>(pts);
    rowsum_kernel<<<NT*N, 128>>>();
    sq_kernel<<<1, 64>>>();

    dim3 gE(NN/256, NT);
    buildM_kernel<<<gE, 256>>>();

    dim3 gG(21, 1, NT);
    // Taylor degree 15, Paterson-Stockmeyer q=4
    // M2: fp32 (elw_g3 + addG read it) + limbs
    gemm_mma<<<gG, 256, SMEMB>>>(0, 0, 1, 0, 0,0,0,0, -1, WM_ALWAYS, WM_ALWAYS);
    // M3: fp32 only (elw_g3 + addG read it); never a GEMM operand
    gemm_mma<<<gG, 256, SMEMB>>>(1, 0, 2, 0, 0,0,0,0, -1, WM_ALWAYS, WM_NEVER);
    // M4: limbs only (pure GEMM operand)
    gemm_mma<<<gG, 256, SMEMB>>>(1, 1, 3, 0, 0,0,0,0, -1, WM_NEVER, WM_ALWAYS);
    elw_g3_kernel<<<gE, 256>>>();   // B4 limbs = G3
    // PS intermediates: limbs only
    gemm_mma<<<gG, 256, SMEMB>>>(3, 4, 5, 1, C8, C9, C10, C11, -1, WM_NEVER, WM_ALWAYS);
    gemm_mma<<<gG, 256, SMEMB>>>(3, 5, 4, 1, C4, C5, C6,  C7,  -1, WM_NEVER, WM_ALWAYS);
    // exp(M): limbs always (squaring operand); fp32 only where q==0 (frob input)
    gemm_mma<<<gG, 256, SMEMB>>>(3, 4, 5, 1, C0, C1, C2,  C3,  -1, WM_Q0, WM_ALWAYS);

    // q = max(s-1,0) squarings; per-t gating inside kernel; ping-pong 5<->4
    // intermediate squarings: limbs only; final squaring per t: fp32 only
    for (int i = 0; i < S_ITERS; i++) {
        int src = (i & 1) ? 4 : 5;
        int dst = (i & 1) ? 5 : 4;
        gemm_mma<<<gG, 256, SMEMB>>>(src, src, dst, 0, 0,0,0,0, i, WM_LAST, WM_NOTLAST);
    }

    frob_kernel<<<NT, 256>>>();
    final_kernel<<<1, 128>>>(out);
}